// round 13
// baseline (speedup 1.0000x reference)
#include <cuda_runtime.h>
#include <math.h>

// ---------------------------------------------------------------------------
// AttentionalGNN: L=18 layers, D=256, H=4 (head dim 64), B=2, N=1024.
// Activations: [b2][C][N] fp32, channel c = d*4 + h.
// Round 13: GEMM widened to 256 threads (8 warps, 4Mx2N, warp tile 16x32)
// on the same 64x64x32 block tile to double latency hiding.
// Attention = round-12 pipelined version (unchanged).
// ---------------------------------------------------------------------------

#define BB   2
#define DD   256
#define NN   1024
#define TEN  (BB*DD*NN)
#define HTEN (BB*512*NN)

// Scratch (device globals). [stream][b2][C][N]
__device__ float g_q  [2*TEN];
__device__ float g_k  [2*TEN];
__device__ float g_v  [2*TEN];
__device__ float g_msg[2*TEN];
__device__ float g_mm [2*TEN];
__device__ float g_h  [2*HTEN];
__device__ float g_stats[2*512*2];

// Pre-split weights (hi/lo), concatenated: Wq|Wk|Wv|Wm|W1|W2
#define SZ_D  (18L*256*256)
#define SZ_1  (18L*512*512)
#define SZ_2  (18L*256*512)
#define OFF_WQ 0L
#define OFF_WK (SZ_D)
#define OFF_WV (2*SZ_D)
#define OFF_WM (3*SZ_D)
#define OFF_W1 (4*SZ_D)
#define OFF_W2 (4*SZ_D + SZ_1)
#define TOTW   (4*SZ_D + SZ_1 + SZ_2)
__device__ float g_whi[TOTW];
__device__ float g_wlo[TOTW];

__device__ __forceinline__ float to_tf32(float x) {
    unsigned u;
    asm("cvt.rna.tf32.f32 %0, %1;" : "=r"(u) : "f"(x));
    return __uint_as_float(u);
}

#define MMA_TF32(acc, af, bf)                                                  \
    asm volatile(                                                              \
        "mma.sync.aligned.m16n8k8.row.col.f32.tf32.tf32.f32 "                  \
        "{%0,%1,%2,%3}, {%4,%5,%6,%7}, {%8,%9}, {%0,%1,%2,%3};"                \
        : "+f"(acc[0]), "+f"(acc[1]), "+f"(acc[2]), "+f"(acc[3])               \
        : "r"(af[0]), "r"(af[1]), "r"(af[2]), "r"(af[3]),                      \
          "r"(bf[0]), "r"(bf[1]))

__device__ __forceinline__ void cpa16(float* dst, const float* src) {
    unsigned sa = (unsigned)__cvta_generic_to_shared(dst);
    asm volatile("cp.async.ca.shared.global [%0], [%1], 16;" :: "r"(sa), "l"(src));
}

// exp on the FMA pipe: round-to-int trick + 2^f poly (deg 6), rel err ~2e-7.
__device__ __forceinline__ float expq(float x) {
    x = fmaxf(x, -80.f);
    float t = fmaf(x, 1.4426950408889634f, 12582912.f);
    float n = t - 12582912.f;
    float f = fmaf(x, 1.4426950408889634f, -n);
    float p = 0.0001540353039338161f;
    p = fmaf(p, f, 0.0013333558146428443f);
    p = fmaf(p, f, 0.009618129107628477f);
    p = fmaf(p, f, 0.05550410866482158f);
    p = fmaf(p, f, 0.2402265069591007f);
    p = fmaf(p, f, 0.6931471805599453f);
    p = fmaf(p, f, 1.0f);
    int ni = __float_as_int(t) - 0x4B400000;
    return __int_as_float(__float_as_int(p) + (ni << 23));
}

// ---------------------------------------------------------------------------
// Weight pre-split
// ---------------------------------------------------------------------------
__global__ __launch_bounds__(256) void presplit_kernel(
    const float* __restrict__ Wq, const float* __restrict__ Wk,
    const float* __restrict__ Wv, const float* __restrict__ Wm,
    const float* __restrict__ W1, const float* __restrict__ W2) {
    long i = ((long)blockIdx.x * 256 + threadIdx.x) * 4;
    if (i >= TOTW) return;
    const float* src; long off = i;
    if      (i < OFF_WK) { src = Wq; }
    else if (i < OFF_WV) { src = Wk; off = i - OFF_WK; }
    else if (i < OFF_WM) { src = Wv; off = i - OFF_WV; }
    else if (i < OFF_W1) { src = Wm; off = i - OFF_WM; }
    else if (i < OFF_W2) { src = W1; off = i - OFF_W1; }
    else                 { src = W2; off = i - OFF_W2; }
    float4 w = *(const float4*)(src + off);
    float4 h, l;
    h.x = to_tf32(w.x); l.x = w.x - h.x;
    h.y = to_tf32(w.y); l.y = w.y - h.y;
    h.z = to_tf32(w.z); l.z = w.z - h.z;
    h.w = to_tf32(w.w); l.w = w.w - h.w;
    *(float4*)(g_whi + i) = h;
    *(float4*)(g_wlo + i) = l;
}

// ---------------------------------------------------------------------------
// Tensor-core GEMM (3xTF32), 2-stage cp.async pipeline, 256 threads.
// Block tile 64x64x32, 8 warps (4M x 2N), warp tile 16x32.
// Dyn smem unchanged: AH/AL 2x[64][36], BS 2x[32][68], BN 2x[64] = 54784 B.
// ---------------------------------------------------------------------------
struct GArgs {
    const float* Whi[3];
    const float* Wlo[3];
    const float* bias[3];
    const float* X0[3][2];
    const float* X1[2];
    const float* res[2];
    const float* bnp[2];
    float*       out[3][2];
    int M, K, K0, use_bn, mtiles;
};

#define GEMM_SMEM (13696 * 4)

__global__ __launch_bounds__(256) void gemm_tc(GArgs a) {
    extern __shared__ __align__(16) float smem[];
    // offsets (floats):  AH: 0 (2x2304) | AL: 4608 | BS: 9216 (2x2176) | BN: 13568 (2x64)

    const int s   = blockIdx.z;
    const int jt  = blockIdx.x;
    const int b2  = jt >> 4;
    const int n0  = (jt & 15) << 6;
    const int mat = blockIdx.y / a.mtiles;
    const int m0  = (blockIdx.y % a.mtiles) << 6;
    const int tid = threadIdx.x;
    const int warp = tid >> 5, lane = tid & 31;
    const int wm = (warp >> 1) << 4;   // 4 M-warps x 16 rows
    const int wn = (warp & 1) << 5;    // 2 N-warps x 32 cols
    const int g = lane >> 2, t = lane & 3;

    const int K = a.K, K0 = a.K0, M = a.M;
    const int use_bn = a.use_bn;
    const float* __restrict__ Whi = a.Whi[mat];
    const float* __restrict__ Wlo = a.Wlo[mat];
    const float* __restrict__ X0  = a.X0[mat][s];
    const float* __restrict__ X1  = a.X1[s];
    const float* __restrict__ bnp = a.bnp[s];

    float acc[4][4];
    #pragma unroll
    for (int ni = 0; ni < 4; ni++)
        #pragma unroll
        for (int r = 0; r < 4; r++) acc[ni][r] = 0.f;

    auto load_tile = [&](int k0, int buf) {
        float* AHb = smem + buf * 2304;
        float* ALb = smem + 4608 + buf * 2304;
        float* BSb = smem + 9216 + buf * 2176;
        float* BNb = smem + 13568 + buf * 64;
        #pragma unroll
        for (int e = tid; e < 512; e += 256) {
            int m  = e >> 3;
            int kq = (e & 7) << 2;
            size_t woff = (size_t)(m0 + m) * K + k0 + kq;
            cpa16(AHb + m * 36 + kq, Whi + woff);
            cpa16(ALb + m * 36 + kq, Wlo + woff);
        }
        #pragma unroll
        for (int e = tid; e < 512; e += 256) {
            int kk = e >> 4;
            int nq = (e & 15) << 2;
            int k = k0 + kk;
            const float* src = (k < K0)
                ? X0 + ((size_t)b2 * K0 + k) * NN + n0 + nq
                : X1 + ((size_t)b2 * (K - K0) + (k - K0)) * NN + n0 + nq;
            cpa16(BSb + kk * 68 + nq, src);
        }
        if (use_bn && tid < 64) BNb[tid] = bnp[2 * k0 + tid];
        asm volatile("cp.async.commit_group;" ::: "memory");
    };

    const int niter = K >> 5;
    load_tile(0, 0);

    for (int it = 0; it < niter; it++) {
        const int buf = it & 1;
        if (it + 1 < niter) {
            load_tile((it + 1) << 5, buf ^ 1);
            asm volatile("cp.async.wait_group 1;" ::: "memory");
        } else {
            asm volatile("cp.async.wait_group 0;" ::: "memory");
        }
        __syncthreads();

        const float* AHb = smem + buf * 2304;
        const float* ALb = smem + 4608 + buf * 2304;
        const float* BSb = smem + 9216 + buf * 2176;
        const float* BNb = smem + 13568 + buf * 64;

        #pragma unroll
        for (int kk = 0; kk < 32; kk += 8) {
            int r0 = wm + g;
            unsigned afh[4], afl[4];
            afh[0] = __float_as_uint(AHb[(r0    ) * 36 + kk + t    ]);
            afh[1] = __float_as_uint(AHb[(r0 + 8) * 36 + kk + t    ]);
            afh[2] = __float_as_uint(AHb[(r0    ) * 36 + kk + t + 4]);
            afh[3] = __float_as_uint(AHb[(r0 + 8) * 36 + kk + t + 4]);
            afl[0] = __float_as_uint(ALb[(r0    ) * 36 + kk + t    ]);
            afl[1] = __float_as_uint(ALb[(r0 + 8) * 36 + kk + t    ]);
            afl[2] = __float_as_uint(ALb[(r0    ) * 36 + kk + t + 4]);
            afl[3] = __float_as_uint(ALb[(r0 + 8) * 36 + kk + t + 4]);
            float sc0 = 1.f, sh0 = 0.f, sc1 = 1.f, sh1 = 0.f;
            if (use_bn) {
                sc0 = BNb[2 * (kk + t)];     sh0 = BNb[2 * (kk + t) + 1];
                sc1 = BNb[2 * (kk + t + 4)]; sh1 = BNb[2 * (kk + t + 4) + 1];
            }
            #pragma unroll
            for (int ni = 0; ni < 4; ni++) {
                int c = wn + ni * 8 + g;
                float b0 = BSb[(kk + t    ) * 68 + c];
                float b1 = BSb[(kk + t + 4) * 68 + c];
                if (use_bn) {
                    b0 = fmaxf(fmaf(b0, sc0, sh0), 0.f);
                    b1 = fmaxf(fmaf(b1, sc1, sh1), 0.f);
                }
                float h0 = to_tf32(b0), h1 = to_tf32(b1);
                unsigned bh2[2] = {__float_as_uint(h0), __float_as_uint(h1)};
                unsigned bl2[2] = {__float_as_uint(b0 - h0), __float_as_uint(b1 - h1)};
                MMA_TF32(acc[ni], afh, bl2);
                MMA_TF32(acc[ni], afl, bh2);
                MMA_TF32(acc[ni], afh, bh2);
            }
        }
        __syncthreads();
    }

    const float* resp = a.res[s];
    const float* biasp = a.bias[mat];
    float* outp = a.out[mat][s];
    #pragma unroll
    for (int half = 0; half < 2; half++) {
        int m = m0 + wm + g + half * 8;
        float bb = biasp[m];
        #pragma unroll
        for (int ni = 0; ni < 4; ni++) {
            int col = n0 + wn + ni * 8 + 2 * t;
            size_t off = ((size_t)b2 * M + m) * NN + col;
            float2 c;
            c.x = acc[ni][2 * half + 0] + bb;
            c.y = acc[ni][2 * half + 1] + bb;
            if (resp) {
                float2 r = *(const float2*)(resp + off);
                c.x += r.x; c.y += r.y;
            }
            *(float2*)(outp + off) = c;
        }
    }
}

// ---------------------------------------------------------------------------
// Tensor-core flash attention (3xTF32), 64-q tiles, software-pipelined
// (round-12 version, unchanged).
// ---------------------------------------------------------------------------
#define ATTN_SMEM (6 * 64 * 68 * 4)

__global__ __launch_bounds__(256) void attn_kernel() {
    extern __shared__ __align__(16) float sm[];
    float (*Qh)[68]  = (float(*)[68])(sm);
    float (*Ql)[68]  = (float(*)[68])(sm + 4352);
    float (*Ks0)[68] = (float(*)[68])(sm + 2 * 4352);
    float (*Ks1)[68] = (float(*)[68])(sm + 3 * 4352);
    float (*Vs)[68]  = (float(*)[68])(sm + 4 * 4352);
    float (*Ps)[68]  = (float(*)[68])(sm + 5 * 4352);
    __shared__ float red_max[2][4][16];
    __shared__ float red_sum[2][4][16];

    const int qt = blockIdx.x;
    const int bh = blockIdx.y;
    const int s  = blockIdx.z;
    const int b2 = bh >> 2, h = bh & 3;
    const int q0 = qt << 6;
    const int tid = threadIdx.x;
    const int warp = tid >> 5, lane = tid & 31;
    const int g = lane >> 2, t = lane & 3;
    const int qw = warp >> 1, kw = warp & 1;
    const int qcol = qw << 4;
    const int kcol = kw << 5;

    size_t base = (size_t)s * TEN + (size_t)b2 * (DD * NN);
    const float* __restrict__ qp = g_q + base;
    const float* __restrict__ kp = g_k + base;
    const float* __restrict__ vp = g_v + base;
    float* mp = g_msg + base;

    for (int e = tid; e < 4096; e += 256) {
        int qi = e & 63, d = e >> 6;
        float v = qp[(size_t)(d * 4 + h) * NN + q0 + qi] * 0.125f;
        float hi = to_tf32(v);
        Qh[d][qi] = hi;
        Ql[d][qi] = v - hi;
    }

    for (int e = tid; e < 1024; e += 256) {
        int d  = e >> 4;
        int c4 = (e & 15) << 2;
        cpa16(&Ks0[d][c4], kp + (size_t)(d * 4 + h) * NN + c4);
    }
    asm volatile("cp.async.commit_group;" ::: "memory");
    for (int e = tid; e < 1024; e += 256) {
        int d  = e >> 4;
        int c4 = (e & 15) << 2;
        cpa16(&Vs[d][c4], vp + (size_t)(d * 4 + h) * NN + c4);
    }
    asm volatile("cp.async.commit_group;" ::: "memory");

    float oacc[4][4] = {};
    float mi2[2] = {-1e30f, -1e30f};
    float li2[2] = {0.f, 0.f};

    for (int kt = 0; kt < 16; kt++) {
        float (*Kb)[68] = (kt & 1) ? Ks1 : Ks0;
        float (*Kn)[68] = (kt & 1) ? Ks0 : Ks1;

        asm volatile("cp.async.wait_group 1;" ::: "memory");
        __syncthreads();

        if (kt + 1 < 16) {
            int m1 = (kt + 1) << 6;
            for (int e = tid; e < 1024; e += 256) {
                int d  = e >> 4;
                int c4 = (e & 15) << 2;
                cpa16(&Kn[d][c4], kp + (size_t)(d * 4 + h) * NN + m1 + c4);
            }
            asm volatile("cp.async.commit_group;" ::: "memory");
        }

        float sacc[4][4] = {};
        #pragma unroll
        for (int kk = 0; kk < 64; kk += 8) {
            unsigned ah[4], al[4];
            ah[0] = __float_as_uint(Qh[kk + t    ][qcol + g    ]);
            ah[1] = __float_as_uint(Qh[kk + t    ][qcol + g + 8]);
            ah[2] = __float_as_uint(Qh[kk + t + 4][qcol + g    ]);
            ah[3] = __float_as_uint(Qh[kk + t + 4][qcol + g + 8]);
            al[0] = __float_as_uint(Ql[kk + t    ][qcol + g    ]);
            al[1] = __float_as_uint(Ql[kk + t    ][qcol + g + 8]);
            al[2] = __float_as_uint(Ql[kk + t + 4][qcol + g    ]);
            al[3] = __float_as_uint(Ql[kk + t + 4][qcol + g + 8]);
            #pragma unroll
            for (int ni = 0; ni < 4; ni++) {
                int c = kcol + ni * 8 + g;
                float b0 = Kb[kk + t    ][c];
                float b1 = Kb[kk + t + 4][c];
                float h0 = to_tf32(b0), h1 = to_tf32(b1);
                unsigned bh2[2] = {__float_as_uint(h0), __float_as_uint(h1)};
                unsigned bl2[2] = {__float_as_uint(b0 - h0), __float_as_uint(b1 - h1)};
                MMA_TF32(sacc[ni], ah, bl2);
                MMA_TF32(sacc[ni], al, bh2);
                MMA_TF32(sacc[ni], ah, bh2);
            }
        }

        float mloc[2] = {-1e30f, -1e30f};
        #pragma unroll
        for (int ni = 0; ni < 4; ni++) {
            mloc[0] = fmaxf(mloc[0], fmaxf(sacc[ni][0], sacc[ni][1]));
            mloc[1] = fmaxf(mloc[1], fmaxf(sacc[ni][2], sacc[ni][3]));
        }
        #pragma unroll
        for (int r = 0; r < 2; r++) {
            mloc[r] = fmaxf(mloc[r], __shfl_xor_sync(0xffffffffu, mloc[r], 1));
            mloc[r] = fmaxf(mloc[r], __shfl_xor_sync(0xffffffffu, mloc[r], 2));
        }
        if (t == 0) {
            red_max[kw][qw][g    ] = mloc[0];
            red_max[kw][qw][g + 8] = mloc[1];
        }
        __syncthreads();
        float mn[2], alpha[2];
        #pragma unroll
        for (int r = 0; r < 2; r++) {
            int row = g + r * 8;
            float mk = fmaxf(red_max[0][qw][row], red_max[1][qw][row]);
            mn[r] = fmaxf(mi2[r], mk);
            alpha[r] = expq(mi2[r] - mn[r]);
            mi2[r] = mn[r];
        }
        float rs[2] = {0.f, 0.f};
        #pragma unroll
        for (int ni = 0; ni < 4; ni++) {
            #pragma unroll
            for (int j = 0; j < 4; j++) {
                int r = j >> 1;
                float p = expq(sacc[ni][j] - mn[r]);
                sacc[ni][j] = p;
                rs[r] += p;
            }
        }
        #pragma unroll
        for (int r = 0; r < 2; r++) {
            rs[r] += __shfl_xor_sync(0xffffffffu, rs[r], 1);
            rs[r] += __shfl_xor_sync(0xffffffffu, rs[r], 2);
        }
        if (t == 0) {
            red_sum[kw][qw][g    ] = rs[0];
            red_sum[kw][qw][g + 8] = rs[1];
        }
        #pragma unroll
        for (int ni = 0; ni < 4; ni++) {
            #pragma unroll
            for (int r = 0; r < 2; r++) {
                int row = qcol + g + r * 8;
                int col = kcol + ni * 8 + 2 * t;
                *(float2*)&Ps[row][col] = make_float2(sacc[ni][2 * r], sacc[ni][2 * r + 1]);
            }
        }
        if (kt + 1 < 16) {
            asm volatile("cp.async.wait_group 1;" ::: "memory");
        } else {
            asm volatile("cp.async.wait_group 0;" ::: "memory");
        }
        __syncthreads();

        #pragma unroll
        for (int r = 0; r < 2; r++) {
            int row = g + r * 8;
            float rstot = red_sum[0][qw][row] + red_sum[1][qw][row];
            li2[r] = li2[r] * alpha[r] + rstot;
        }
        #pragma unroll
        for (int ni = 0; ni < 4; ni++) {
            oacc[ni][0] *= alpha[0]; oacc[ni][1] *= alpha[0];
            oacc[ni][2] *= alpha[1]; oacc[ni][3] *= alpha[1];
        }

        #pragma unroll
        for (int kk = 0; kk < 64; kk += 8) {
            float a0 = Ps[qcol + g    ][kk + t    ];
            float a1 = Ps[qcol + g + 8][kk + t    ];
            float a2 = Ps[qcol + g    ][kk + t + 4];
            float a3 = Ps[qcol + g + 8][kk + t + 4];
            float ah0 = to_tf32(a0), ah1 = to_tf32(a1);
            float ah2 = to_tf32(a2), ah3 = to_tf32(a3);
            unsigned ah[4] = {__float_as_uint(ah0), __float_as_uint(ah1),
                              __float_as_uint(ah2), __float_as_uint(ah3)};
            unsigned al[4] = {__float_as_uint(a0 - ah0), __float_as_uint(a1 - ah1),
                              __float_as_uint(a2 - ah2), __float_as_uint(a3 - ah3)};
            #pragma unroll
            for (int ni = 0; ni < 4; ni++) {
                int c = kcol + ni * 8 + g;
                float b0 = Vs[c][kk + t    ];
                float b1 = Vs[c][kk + t + 4];
                float h0 = to_tf32(b0), h1 = to_tf32(b1);
                unsigned bh2[2] = {__float_as_uint(h0), __float_as_uint(h1)};
                unsigned bl2[2] = {__float_as_uint(b0 - h0), __float_as_uint(b1 - h1)};
                MMA_TF32(oacc[ni], ah, bl2);
                MMA_TF32(oacc[ni], al, bh2);
                MMA_TF32(oacc[ni], ah, bh2);
            }
        }

        __syncthreads();
        if (kt + 1 < 16) {
            int m1 = (kt + 1) << 6;
            for (int e = tid; e < 1024; e += 256) {
                int d  = e >> 4;
                int c4 = (e & 15) << 2;
                cpa16(&Vs[d][c4], vp + (size_t)(d * 4 + h) * NN + m1 + c4);
            }
            asm volatile("cp.async.commit_group;" ::: "memory");
        }
    }

    float inv[2] = {1.f / li2[0], 1.f / li2[1]};
    #pragma unroll
    for (int ni = 0; ni < 4; ni++) {
        #pragma unroll
        for (int j = 0; j < 4; j++) {
            int r = j >> 1;
            int row_q = qcol + g + r * 8;
            int col_d = kcol + ni * 8 + 2 * t + (j & 1);
            Ps[col_d][row_q] = oacc[ni][j] * inv[r];
        }
    }
    __syncthreads();
    for (int e = tid; e < 4096; e += 256) {
        int qi = e & 63, d = e >> 6;
        mp[(size_t)(d * 4 + h) * NN + q0 + qi] = Ps[d][qi];
    }
}

// ---------------------------------------------------------------------------
// BatchNorm stats (unchanged).
// ---------------------------------------------------------------------------
__global__ __launch_bounds__(256) void bn_stats_kernel(const float* __restrict__ g1,
                                                       const float* __restrict__ be1) {
    const int c = blockIdx.x;
    const int s = blockIdx.y;
    const float* hp = g_h + (size_t)s * HTEN;
    int tid = threadIdx.x;
    float sum = 0.f, sq = 0.f;
    for (int idx = tid; idx < 2048; idx += 256) {
        int b2 = idx >> 10, n = idx & 1023;
        float v = hp[((size_t)b2 * 512 + c) * NN + n];
        sum += v;
        sq = fmaf(v, v, sq);
    }
    #pragma unroll
    for (int w = 16; w; w >>= 1) {
        sum += __shfl_xor_sync(0xffffffffu, sum, w);
        sq  += __shfl_xor_sync(0xffffffffu, sq,  w);
    }
    __shared__ float ssum[8], ssq[8];
    int wid = tid >> 5, lane = tid & 31;
    if (lane == 0) { ssum[wid] = sum; ssq[wid] = sq; }
    __syncthreads();
    if (tid == 0) {
        float S = 0.f, Q = 0.f;
        #pragma unroll
        for (int i = 0; i < 8; i++) { S += ssum[i]; Q += ssq[i]; }
        float mean = S * (1.f / 2048.f);
        float var  = Q * (1.f / 2048.f) - mean * mean;
        float rstd = rsqrtf(var + 1e-5f);
        float sc = rstd * g1[c];
        float sh = be1[c] - mean * sc;
        g_stats[(s * 512 + c) * 2 + 0] = sc;
        g_stats[(s * 512 + c) * 2 + 1] = sh;
    }
}

// ---------------------------------------------------------------------------
// Host orchestration
// ---------------------------------------------------------------------------
extern "C" void kernel_launch(void* const* d_in, const int* in_sizes, int n_in,
                              void* d_out, int out_size) {
    const float* desc0 = (const float*)d_in[0];
    const float* desc1 = (const float*)d_in[1];
    const float* Wq  = (const float*)d_in[2];
    const float* bq  = (const float*)d_in[3];
    const float* Wk  = (const float*)d_in[4];
    const float* bk  = (const float*)d_in[5];
    const float* Wv  = (const float*)d_in[6];
    const float* bv  = (const float*)d_in[7];
    const float* Wm  = (const float*)d_in[8];
    const float* bm  = (const float*)d_in[9];
    const float* W1  = (const float*)d_in[10];
    const float* b1  = (const float*)d_in[11];
    const float* g1  = (const float*)d_in[12];
    const float* be1 = (const float*)d_in[13];
    const float* W2  = (const float*)d_in[14];
    const float* b2  = (const float*)d_in[15];
    float* out = (float*)d_out;

    float *qb, *kb, *vb, *msgb, *mmb, *hb, *statsb, *whi, *wlo;
    cudaGetSymbolAddress((void**)&qb,    g_q);
    cudaGetSymbolAddress((void**)&kb,    g_k);
    cudaGetSymbolAddress((void**)&vb,    g_v);
    cudaGetSymbolAddress((void**)&msgb,  g_msg);
    cudaGetSymbolAddress((void**)&mmb,   g_mm);
    cudaGetSymbolAddress((void**)&hb,    g_h);
    cudaGetSymbolAddress((void**)&statsb, g_stats);
    cudaGetSymbolAddress((void**)&whi,   g_whi);
    cudaGetSymbolAddress((void**)&wlo,   g_wlo);

    cudaFuncSetAttribute(attn_kernel,
                         cudaFuncAttributeMaxDynamicSharedMemorySize, ATTN_SMEM);
    cudaFuncSetAttribute(gemm_tc,
                         cudaFuncAttributeMaxDynamicSharedMemorySize, GEMM_SMEM);

    presplit_kernel<<<(int)((TOTW / 4 + 255) / 256), 256>>>(Wq, Wk, Wv, Wm, W1, W2);

    cudaMemcpyAsync(out + 2 * (size_t)TEN, desc0, TEN * sizeof(float),
                    cudaMemcpyDeviceToDevice, 0);
    cudaMemcpyAsync(out + 3 * (size_t)TEN, desc1, TEN * sizeof(float),
                    cudaMemcpyDeviceToDevice, 0);

    const float* xa = desc0;
    const float* xb = desc1;

    for (int i = 0; i < 18; i++) {
        const float *sa, *sb, *ra, *rb;
        float *oa, *ob;
        if (i == 0) {
            sa = xa; sb = xb; ra = desc0; rb = desc1;
            oa = out;            ob = out + (size_t)TEN;
        } else if (i == 1) {
            sa = xb; sb = xa; ra = desc0; rb = desc1;
            oa = out + 4 * (size_t)TEN; ob = out + 5 * (size_t)TEN;
        } else {
            if ((i & 1) == 0) { sa = xa; sb = xb; }
            else              { sa = xb; sb = xa; }
            ra = xa; rb = xb;
            oa = out + (size_t)(2 + 2 * i) * TEN;
            ob = oa + (size_t)TEN;
        }

        const float* Wq_hi = whi + OFF_WQ + (size_t)i * 65536;
        const float* Wq_lo = wlo + OFF_WQ + (size_t)i * 65536;
        const float* Wk_hi = whi + OFF_WK + (size_t)i * 65536;
        const float* Wk_lo = wlo + OFF_WK + (size_t)i * 65536;
        const float* Wv_hi = whi + OFF_WV + (size_t)i * 65536;
        const float* Wv_lo = wlo + OFF_WV + (size_t)i * 65536;
        const float* Wm_hi = whi + OFF_WM + (size_t)i * 65536;
        const float* Wm_lo = wlo + OFF_WM + (size_t)i * 65536;
        const float* W1_hi = whi + OFF_W1 + (size_t)i * 262144;
        const float* W1_lo = wlo + OFF_W1 + (size_t)i * 262144;
        const float* W2_hi = whi + OFF_W2 + (size_t)i * 131072;
        const float* W2_lo = wlo + OFF_W2 + (size_t)i * 131072;
        const float* bq_i = bq + (size_t)i * 256;
        const float* bk_i = bk + (size_t)i * 256;
        const float* bv_i = bv + (size_t)i * 256;
        const float* bm_i = bm + (size_t)i * 256;
        const float* b1_i = b1 + (size_t)i * 512;
        const float* b2_i = b2 + (size_t)i * 256;
        const float* g1_i = g1 + (size_t)i * 512;
        const float* be_i = be1 + (size_t)i * 512;

        GArgs ga = {};
        ga.bnp[0] = statsb; ga.bnp[1] = statsb + 1024;

        // q/k/v merged
        ga.Whi[0] = Wq_hi; ga.Wlo[0] = Wq_lo; ga.bias[0] = bq_i;
        ga.Whi[1] = Wk_hi; ga.Wlo[1] = Wk_lo; ga.bias[1] = bk_i;
        ga.Whi[2] = Wv_hi; ga.Wlo[2] = Wv_lo; ga.bias[2] = bv_i;
        ga.X0[0][0] = xa; ga.X0[0][1] = xb;
        ga.X0[1][0] = sa; ga.X0[1][1] = sb;
        ga.X0[2][0] = sa; ga.X0[2][1] = sb;
        ga.out[0][0] = qb; ga.out[0][1] = qb + TEN;
        ga.out[1][0] = kb; ga.out[1][1] = kb + TEN;
        ga.out[2][0] = vb; ga.out[2][1] = vb + TEN;
        ga.X1[0] = ga.X1[1] = nullptr;
        ga.res[0] = ga.res[1] = nullptr;
        ga.M = 256; ga.K = 256; ga.K0 = 256; ga.use_bn = 0; ga.mtiles = 4;
        gemm_tc<<<dim3(32, 12, 2), 256, GEMM_SMEM>>>(ga);

        // attention
        attn_kernel<<<dim3(16, 8, 2), 256, ATTN_SMEM>>>();

        // msg projection
        ga.Whi[0] = Wm_hi; ga.Wlo[0] = Wm_lo; ga.bias[0] = bm_i;
        ga.X0[0][0] = msgb; ga.X0[0][1] = msgb + TEN;
        ga.out[0][0] = mmb; ga.out[0][1] = mmb + TEN;
        ga.M = 256; ga.K = 256; ga.K0 = 256; ga.use_bn = 0; ga.mtiles = 4;
        gemm_tc<<<dim3(32, 4, 2), 256, GEMM_SMEM>>>(ga);

        // h = W1 [x; msg] + b1
        ga.Whi[0] = W1_hi; ga.Wlo[0] = W1_lo; ga.bias[0] = b1_i;
        ga.X0[0][0] = xa; ga.X0[0][1] = xb;
        ga.X1[0] = mmb; ga.X1[1] = mmb + TEN;
        ga.out[0][0] = hb; ga.out[0][1] = hb + HTEN;
        ga.M = 512; ga.K = 512; ga.K0 = 256; ga.use_bn = 0; ga.mtiles = 8;
        gemm_tc<<<dim3(32, 8, 2), 256, GEMM_SMEM>>>(ga);

        // BN stats
        bn_stats_kernel<<<dim3(512, 2), 256>>>(g1_i, be_i);

        // out = res + W2 relu(BN(h)) + b2
        ga.Whi[0] = W2_hi; ga.Wlo[0] = W2_lo; ga.bias[0] = b2_i;
        ga.X0[0][0] = hb; ga.X0[0][1] = hb + HTEN;
        ga.X1[0] = ga.X1[1] = nullptr;
        ga.res[0] = ra; ga.res[1] = rb;
        ga.out[0][0] = oa; ga.out[0][1] = ob;
        ga.M = 256; ga.K = 512; ga.K0 = 512; ga.use_bn = 1; ga.mtiles = 4;
        gemm_tc<<<dim3(32, 4, 2), 256, GEMM_SMEM>>>(ga);
        ga.res[0] = ga.res[1] = nullptr;

        xa = oa; xb = ob;
    }
}

// round 14
// speedup vs baseline: 1.1443x; 1.1443x over previous
#include <cuda_runtime.h>
#include <math.h>

// ---------------------------------------------------------------------------
// AttentionalGNN: L=18 layers, D=256, H=4 (head dim 64), B=2, N=1024.
// Activations: [b2][C][N] fp32, channel c = d*4 + h.
// Round 14: GEMM reverted to 128-thread r12 config. Wm GEMM eliminated by
// folding into W1:  h = [W1a | W1b*Wm]·[x; attnout] + (b1 + W1b*bm).
// W1b*Wm precomputed once per launch (3xTF32) into the W1 weight slot.
// ---------------------------------------------------------------------------

#define BB   2
#define DD   256
#define NN   1024
#define TEN  (BB*DD*NN)
#define HTEN (BB*512*NN)

// Scratch (device globals). [stream][b2][C][N]
__device__ float g_q  [2*TEN];
__device__ float g_k  [2*TEN];
__device__ float g_v  [2*TEN];
__device__ float g_msg[2*TEN];
__device__ float g_h  [2*HTEN];
__device__ float g_stats[2*512*2];
__device__ float g_b1eff[18*512];

// Pre-split weights (hi/lo), concatenated: Wq|Wk|Wv|Wm|W1|W2
#define SZ_D  (18L*256*256)
#define SZ_1  (18L*512*512)
#define SZ_2  (18L*256*512)
#define OFF_WQ 0L
#define OFF_WK (SZ_D)
#define OFF_WV (2*SZ_D)
#define OFF_WM (3*SZ_D)
#define OFF_W1 (4*SZ_D)
#define OFF_W2 (4*SZ_D + SZ_1)
#define TOTW   (4*SZ_D + SZ_1 + SZ_2)
__device__ float g_whi[TOTW];
__device__ float g_wlo[TOTW];

__device__ __forceinline__ float to_tf32(float x) {
    unsigned u;
    asm("cvt.rna.tf32.f32 %0, %1;" : "=r"(u) : "f"(x));
    return __uint_as_float(u);
}

#define MMA_TF32(acc, af, bf)                                                  \
    asm volatile(                                                              \
        "mma.sync.aligned.m16n8k8.row.col.f32.tf32.tf32.f32 "                  \
        "{%0,%1,%2,%3}, {%4,%5,%6,%7}, {%8,%9}, {%0,%1,%2,%3};"                \
        : "+f"(acc[0]), "+f"(acc[1]), "+f"(acc[2]), "+f"(acc[3])               \
        : "r"(af[0]), "r"(af[1]), "r"(af[2]), "r"(af[3]),                      \
          "r"(bf[0]), "r"(bf[1]))

__device__ __forceinline__ void cpa16(float* dst, const float* src) {
    unsigned sa = (unsigned)__cvta_generic_to_shared(dst);
    asm volatile("cp.async.ca.shared.global [%0], [%1], 16;" :: "r"(sa), "l"(src));
}

// exp on the FMA pipe: round-to-int trick + 2^f poly (deg 6), rel err ~2e-7.
__device__ __forceinline__ float expq(float x) {
    x = fmaxf(x, -80.f);
    float t = fmaf(x, 1.4426950408889634f, 12582912.f);
    float n = t - 12582912.f;
    float f = fmaf(x, 1.4426950408889634f, -n);
    float p = 0.0001540353039338161f;
    p = fmaf(p, f, 0.0013333558146428443f);
    p = fmaf(p, f, 0.009618129107628477f);
    p = fmaf(p, f, 0.05550410866482158f);
    p = fmaf(p, f, 0.2402265069591007f);
    p = fmaf(p, f, 0.6931471805599453f);
    p = fmaf(p, f, 1.0f);
    int ni = __float_as_int(t) - 0x4B400000;
    return __int_as_float(__float_as_int(p) + (ni << 23));
}

// ---------------------------------------------------------------------------
// Weight pre-split
// ---------------------------------------------------------------------------
__global__ __launch_bounds__(256) void presplit_kernel(
    const float* __restrict__ Wq, const float* __restrict__ Wk,
    const float* __restrict__ Wv, const float* __restrict__ Wm,
    const float* __restrict__ W1, const float* __restrict__ W2) {
    long i = ((long)blockIdx.x * 256 + threadIdx.x) * 4;
    if (i >= TOTW) return;
    const float* src; long off = i;
    if      (i < OFF_WK) { src = Wq; }
    else if (i < OFF_WV) { src = Wk; off = i - OFF_WK; }
    else if (i < OFF_WM) { src = Wv; off = i - OFF_WV; }
    else if (i < OFF_W1) { src = Wm; off = i - OFF_WM; }
    else if (i < OFF_W2) { src = W1; off = i - OFF_W1; }
    else                 { src = W2; off = i - OFF_W2; }
    float4 w = *(const float4*)(src + off);
    float4 h, l;
    h.x = to_tf32(w.x); l.x = w.x - h.x;
    h.y = to_tf32(w.y); l.y = w.y - h.y;
    h.z = to_tf32(w.z); l.z = w.z - h.z;
    h.w = to_tf32(w.w); l.w = w.w - h.w;
    *(float4*)(g_whi + i) = h;
    *(float4*)(g_wlo + i) = l;
}

// ---------------------------------------------------------------------------
// W1m precompute: for each layer, W1m[m][i] = sum_o W1[m][256+o] * Wm[o][i],
// written (hi/lo split) into the W1 weight slot at cols 256:512.
// grid = (4 n-tiles, 8 m-tiles, 18 layers), 128 threads, 64x64x32 tiles.
// Runs AFTER presplit (stream order) so its writes win.
// ---------------------------------------------------------------------------
__global__ __launch_bounds__(128) void fuse_w1m_kernel(
    const float* __restrict__ W1, const float* __restrict__ Wm) {
    __shared__ float Ah[64][36], Al[64][36];
    __shared__ float Bh[32][68], Bl[32][68];
    const int layer = blockIdx.z;
    const int n0 = blockIdx.x << 6;
    const int m0 = blockIdx.y << 6;
    const float* W1p = W1 + (size_t)layer * 262144;
    const float* Wmp = Wm + (size_t)layer * 65536;
    const int tid = threadIdx.x;
    const int warp = tid >> 5, lane = tid & 31;
    const int wm = (warp >> 1) << 5;
    const int wn = (warp & 1) << 5;
    const int g = lane >> 2, t = lane & 3;

    float acc[2][4][4];
    #pragma unroll
    for (int mi = 0; mi < 2; mi++)
        #pragma unroll
        for (int ni = 0; ni < 4; ni++)
            #pragma unroll
            for (int r = 0; r < 4; r++) acc[mi][ni][r] = 0.f;

    for (int k0 = 0; k0 < 256; k0 += 32) {
        #pragma unroll
        for (int e = tid; e < 512; e += 128) {
            int m  = e >> 3;
            int kq = (e & 7) << 2;
            float4 w = *(const float4*)&W1p[(size_t)(m0 + m) * 512 + 256 + k0 + kq];
            float wa[4] = {w.x, w.y, w.z, w.w};
            #pragma unroll
            for (int q = 0; q < 4; q++) {
                float hi = to_tf32(wa[q]);
                Ah[m][kq + q] = hi;
                Al[m][kq + q] = wa[q] - hi;
            }
        }
        #pragma unroll
        for (int e = tid; e < 512; e += 128) {
            int kk = e >> 4;
            int nq = (e & 15) << 2;
            float4 v = *(const float4*)&Wmp[(size_t)(k0 + kk) * 256 + n0 + nq];
            float va[4] = {v.x, v.y, v.z, v.w};
            #pragma unroll
            for (int q = 0; q < 4; q++) {
                float hi = to_tf32(va[q]);
                Bh[kk][nq + q] = hi;
                Bl[kk][nq + q] = va[q] - hi;
            }
        }
        __syncthreads();
        #pragma unroll
        for (int kk = 0; kk < 32; kk += 8) {
            unsigned afh[2][4], afl[2][4];
            #pragma unroll
            for (int mi = 0; mi < 2; mi++) {
                int r0 = wm + mi * 16 + g;
                afh[mi][0] = __float_as_uint(Ah[r0    ][kk + t    ]);
                afh[mi][1] = __float_as_uint(Ah[r0 + 8][kk + t    ]);
                afh[mi][2] = __float_as_uint(Ah[r0    ][kk + t + 4]);
                afh[mi][3] = __float_as_uint(Ah[r0 + 8][kk + t + 4]);
                afl[mi][0] = __float_as_uint(Al[r0    ][kk + t    ]);
                afl[mi][1] = __float_as_uint(Al[r0 + 8][kk + t    ]);
                afl[mi][2] = __float_as_uint(Al[r0    ][kk + t + 4]);
                afl[mi][3] = __float_as_uint(Al[r0 + 8][kk + t + 4]);
            }
            #pragma unroll
            for (int ni = 0; ni < 4; ni++) {
                int c = wn + ni * 8 + g;
                unsigned bh2[2] = {__float_as_uint(Bh[kk + t][c]),
                                   __float_as_uint(Bh[kk + t + 4][c])};
                unsigned bl2[2] = {__float_as_uint(Bl[kk + t][c]),
                                   __float_as_uint(Bl[kk + t + 4][c])};
                #pragma unroll
                for (int mi = 0; mi < 2; mi++) {
                    MMA_TF32(acc[mi][ni], afh[mi], bl2);
                    MMA_TF32(acc[mi][ni], afl[mi], bh2);
                    MMA_TF32(acc[mi][ni], afh[mi], bh2);
                }
            }
        }
        __syncthreads();
    }

    // write split result into W1 slot cols 256:512
    size_t base = OFF_W1 + (size_t)layer * 262144;
    #pragma unroll
    for (int mi = 0; mi < 2; mi++) {
        #pragma unroll
        for (int half = 0; half < 2; half++) {
            int m = m0 + wm + mi * 16 + g + half * 8;
            #pragma unroll
            for (int ni = 0; ni < 4; ni++) {
                int col = n0 + wn + ni * 8 + 2 * t;
                size_t off = base + (size_t)m * 512 + 256 + col;
                float v0 = acc[mi][ni][2 * half + 0];
                float v1 = acc[mi][ni][2 * half + 1];
                float h0 = to_tf32(v0), h1 = to_tf32(v1);
                *(float2*)(g_whi + off) = make_float2(h0, h1);
                *(float2*)(g_wlo + off) = make_float2(v0 - h0, v1 - h1);
            }
        }
    }
}

// b1eff[l][m] = b1[l][m] + sum_o W1[l][m][256+o] * bm[l][o]
__global__ __launch_bounds__(512) void b1eff_kernel(
    const float* __restrict__ W1, const float* __restrict__ b1,
    const float* __restrict__ bm) {
    int layer = blockIdx.x;
    int m = threadIdx.x;
    const float* w = W1 + (size_t)layer * 262144 + (size_t)m * 512 + 256;
    const float* bmp = bm + layer * 256;
    float s = b1[layer * 512 + m];
    for (int o = 0; o < 256; o++) s = fmaf(w[o], bmp[o], s);
    g_b1eff[layer * 512 + m] = s;
}

// ---------------------------------------------------------------------------
// Tensor-core GEMM (3xTF32), 2-stage cp.async pipeline, 128 threads
// (round-12 proven config).
// ---------------------------------------------------------------------------
struct GArgs {
    const float* Whi[3];
    const float* Wlo[3];
    const float* bias[3];
    const float* X0[3][2];
    const float* X1[2];
    const float* res[2];
    const float* bnp[2];
    float*       out[3][2];
    int M, K, K0, use_bn, mtiles;
};

#define GEMM_SMEM (13696 * 4)

__global__ __launch_bounds__(128) void gemm_tc(GArgs a) {
    extern __shared__ __align__(16) float smem[];
    // offsets (floats):  AH: 0 (2x2304) | AL: 4608 | BS: 9216 (2x2176) | BN: 13568 (2x64)

    const int s   = blockIdx.z;
    const int jt  = blockIdx.x;
    const int b2  = jt >> 4;
    const int n0  = (jt & 15) << 6;
    const int mat = blockIdx.y / a.mtiles;
    const int m0  = (blockIdx.y % a.mtiles) << 6;
    const int tid = threadIdx.x;
    const int warp = tid >> 5, lane = tid & 31;
    const int wm = (warp >> 1) << 5;
    const int wn = (warp & 1) << 5;
    const int g = lane >> 2, t = lane & 3;

    const int K = a.K, K0 = a.K0, M = a.M;
    const int use_bn = a.use_bn;
    const float* __restrict__ Whi = a.Whi[mat];
    const float* __restrict__ Wlo = a.Wlo[mat];
    const float* __restrict__ X0  = a.X0[mat][s];
    const float* __restrict__ X1  = a.X1[s];
    const float* __restrict__ bnp = a.bnp[s];

    float acc[2][4][4];
    #pragma unroll
    for (int mi = 0; mi < 2; mi++)
        #pragma unroll
        for (int ni = 0; ni < 4; ni++)
            #pragma unroll
            for (int r = 0; r < 4; r++) acc[mi][ni][r] = 0.f;

    auto load_tile = [&](int k0, int buf) {
        float* AHb = smem + buf * 2304;
        float* ALb = smem + 4608 + buf * 2304;
        float* BSb = smem + 9216 + buf * 2176;
        float* BNb = smem + 13568 + buf * 64;
        #pragma unroll
        for (int e = tid; e < 512; e += 128) {
            int m  = e >> 3;
            int kq = (e & 7) << 2;
            size_t woff = (size_t)(m0 + m) * K + k0 + kq;
            cpa16(AHb + m * 36 + kq, Whi + woff);
            cpa16(ALb + m * 36 + kq, Wlo + woff);
        }
        #pragma unroll
        for (int e = tid; e < 512; e += 128) {
            int kk = e >> 4;
            int nq = (e & 15) << 2;
            int k = k0 + kk;
            const float* src = (k < K0)
                ? X0 + ((size_t)b2 * K0 + k) * NN + n0 + nq
                : X1 + ((size_t)b2 * (K - K0) + (k - K0)) * NN + n0 + nq;
            cpa16(BSb + kk * 68 + nq, src);
        }
        if (use_bn && tid < 64) BNb[tid] = bnp[2 * k0 + tid];
        asm volatile("cp.async.commit_group;" ::: "memory");
    };

    const int niter = K >> 5;
    load_tile(0, 0);

    for (int it = 0; it < niter; it++) {
        const int buf = it & 1;
        if (it + 1 < niter) {
            load_tile((it + 1) << 5, buf ^ 1);
            asm volatile("cp.async.wait_group 1;" ::: "memory");
        } else {
            asm volatile("cp.async.wait_group 0;" ::: "memory");
        }
        __syncthreads();

        const float* AHb = smem + buf * 2304;
        const float* ALb = smem + 4608 + buf * 2304;
        const float* BSb = smem + 9216 + buf * 2176;
        const float* BNb = smem + 13568 + buf * 64;

        #pragma unroll
        for (int kk = 0; kk < 32; kk += 8) {
            unsigned afh[2][4], afl[2][4];
            #pragma unroll
            for (int mi = 0; mi < 2; mi++) {
                int r0 = wm + mi * 16 + g;
                afh[mi][0] = __float_as_uint(AHb[(r0    ) * 36 + kk + t    ]);
                afh[mi][1] = __float_as_uint(AHb[(r0 + 8) * 36 + kk + t    ]);
                afh[mi][2] = __float_as_uint(AHb[(r0    ) * 36 + kk + t + 4]);
                afh[mi][3] = __float_as_uint(AHb[(r0 + 8) * 36 + kk + t + 4]);
                afl[mi][0] = __float_as_uint(ALb[(r0    ) * 36 + kk + t    ]);
                afl[mi][1] = __float_as_uint(ALb[(r0 + 8) * 36 + kk + t    ]);
                afl[mi][2] = __float_as_uint(ALb[(r0    ) * 36 + kk + t + 4]);
                afl[mi][3] = __float_as_uint(ALb[(r0 + 8) * 36 + kk + t + 4]);
            }
            float sc0 = 1.f, sh0 = 0.f, sc1 = 1.f, sh1 = 0.f;
            if (use_bn) {
                sc0 = BNb[2 * (kk + t)];     sh0 = BNb[2 * (kk + t) + 1];
                sc1 = BNb[2 * (kk + t + 4)]; sh1 = BNb[2 * (kk + t + 4) + 1];
            }
            #pragma unroll
            for (int ni = 0; ni < 4; ni++) {
                int c = wn + ni * 8 + g;
                float b0 = BSb[(kk + t    ) * 68 + c];
                float b1 = BSb[(kk + t + 4) * 68 + c];
                if (use_bn) {
                    b0 = fmaxf(fmaf(b0, sc0, sh0), 0.f);
                    b1 = fmaxf(fmaf(b1, sc1, sh1), 0.f);
                }
                float h0 = to_tf32(b0), h1 = to_tf32(b1);
                unsigned bh2[2] = {__float_as_uint(h0), __float_as_uint(h1)};
                unsigned bl2[2] = {__float_as_uint(b0 - h0), __float_as_uint(b1 - h1)};
                #pragma unroll
                for (int mi = 0; mi < 2; mi++) {
                    MMA_TF32(acc[mi][ni], afh[mi], bl2);
                    MMA_TF32(acc[mi][ni], afl[mi], bh2);
                    MMA_TF32(acc[mi][ni], afh[mi], bh2);
                }
            }
        }
        __syncthreads();
    }

    const float* resp = a.res[s];
    const float* biasp = a.bias[mat];
    float* outp = a.out[mat][s];
    #pragma unroll
    for (int mi = 0; mi < 2; mi++) {
        #pragma unroll
        for (int half = 0; half < 2; half++) {
            int m = m0 + wm + mi * 16 + g + half * 8;
            float bb = biasp[m];
            #pragma unroll
            for (int ni = 0; ni < 4; ni++) {
                int col = n0 + wn + ni * 8 + 2 * t;
                size_t off = ((size_t)b2 * M + m) * NN + col;
                float2 c;
                c.x = acc[mi][ni][2 * half + 0] + bb;
                c.y = acc[mi][ni][2 * half + 1] + bb;
                if (resp) {
                    float2 r = *(const float2*)(resp + off);
                    c.x += r.x; c.y += r.y;
                }
                *(float2*)(outp + off) = c;
            }
        }
    }
}

// ---------------------------------------------------------------------------
// Tensor-core flash attention (3xTF32), 64-q tiles, software-pipelined
// (round-12 version, unchanged).
// ---------------------------------------------------------------------------
#define ATTN_SMEM (6 * 64 * 68 * 4)

__global__ __launch_bounds__(256) void attn_kernel() {
    extern __shared__ __align__(16) float sm[];
    float (*Qh)[68]  = (float(*)[68])(sm);
    float (*Ql)[68]  = (float(*)[68])(sm + 4352);
    float (*Ks0)[68] = (float(*)[68])(sm + 2 * 4352);
    float (*Ks1)[68] = (float(*)[68])(sm + 3 * 4352);
    float (*Vs)[68]  = (float(*)[68])(sm + 4 * 4352);
    float (*Ps)[68]  = (float(*)[68])(sm + 5 * 4352);
    __shared__ float red_max[2][4][16];
    __shared__ float red_sum[2][4][16];

    const int qt = blockIdx.x;
    const int bh = blockIdx.y;
    const int s  = blockIdx.z;
    const int b2 = bh >> 2, h = bh & 3;
    const int q0 = qt << 6;
    const int tid = threadIdx.x;
    const int warp = tid >> 5, lane = tid & 31;
    const int g = lane >> 2, t = lane & 3;
    const int qw = warp >> 1, kw = warp & 1;
    const int qcol = qw << 4;
    const int kcol = kw << 5;

    size_t base = (size_t)s * TEN + (size_t)b2 * (DD * NN);
    const float* __restrict__ qp = g_q + base;
    const float* __restrict__ kp = g_k + base;
    const float* __restrict__ vp = g_v + base;
    float* mp = g_msg + base;

    for (int e = tid; e < 4096; e += 256) {
        int qi = e & 63, d = e >> 6;
        float v = qp[(size_t)(d * 4 + h) * NN + q0 + qi] * 0.125f;
        float hi = to_tf32(v);
        Qh[d][qi] = hi;
        Ql[d][qi] = v - hi;
    }

    for (int e = tid; e < 1024; e += 256) {
        int d  = e >> 4;
        int c4 = (e & 15) << 2;
        cpa16(&Ks0[d][c4], kp + (size_t)(d * 4 + h) * NN + c4);
    }
    asm volatile("cp.async.commit_group;" ::: "memory");
    for (int e = tid; e < 1024; e += 256) {
        int d  = e >> 4;
        int c4 = (e & 15) << 2;
        cpa16(&Vs[d][c4], vp + (size_t)(d * 4 + h) * NN + c4);
    }
    asm volatile("cp.async.commit_group;" ::: "memory");

    float oacc[4][4] = {};
    float mi2[2] = {-1e30f, -1e30f};
    float li2[2] = {0.f, 0.f};

    for (int kt = 0; kt < 16; kt++) {
        float (*Kb)[68] = (kt & 1) ? Ks1 : Ks0;
        float (*Kn)[68] = (kt & 1) ? Ks0 : Ks1;

        asm volatile("cp.async.wait_group 1;" ::: "memory");
        __syncthreads();

        if (kt + 1 < 16) {
            int m1 = (kt + 1) << 6;
            for (int e = tid; e < 1024; e += 256) {
                int d  = e >> 4;
                int c4 = (e & 15) << 2;
                cpa16(&Kn[d][c4], kp + (size_t)(d * 4 + h) * NN + m1 + c4);
            }
            asm volatile("cp.async.commit_group;" ::: "memory");
        }

        float sacc[4][4] = {};
        #pragma unroll
        for (int kk = 0; kk < 64; kk += 8) {
            unsigned ah[4], al[4];
            ah[0] = __float_as_uint(Qh[kk + t    ][qcol + g    ]);
            ah[1] = __float_as_uint(Qh[kk + t    ][qcol + g + 8]);
            ah[2] = __float_as_uint(Qh[kk + t + 4][qcol + g    ]);
            ah[3] = __float_as_uint(Qh[kk + t + 4][qcol + g + 8]);
            al[0] = __float_as_uint(Ql[kk + t    ][qcol + g    ]);
            al[1] = __float_as_uint(Ql[kk + t    ][qcol + g + 8]);
            al[2] = __float_as_uint(Ql[kk + t + 4][qcol + g    ]);
            al[3] = __float_as_uint(Ql[kk + t + 4][qcol + g + 8]);
            #pragma unroll
            for (int ni = 0; ni < 4; ni++) {
                int c = kcol + ni * 8 + g;
                float b0 = Kb[kk + t    ][c];
                float b1 = Kb[kk + t + 4][c];
                float h0 = to_tf32(b0), h1 = to_tf32(b1);
                unsigned bh2[2] = {__float_as_uint(h0), __float_as_uint(h1)};
                unsigned bl2[2] = {__float_as_uint(b0 - h0), __float_as_uint(b1 - h1)};
                MMA_TF32(sacc[ni], ah, bl2);
                MMA_TF32(sacc[ni], al, bh2);
                MMA_TF32(sacc[ni], ah, bh2);
            }
        }

        float mloc[2] = {-1e30f, -1e30f};
        #pragma unroll
        for (int ni = 0; ni < 4; ni++) {
            mloc[0] = fmaxf(mloc[0], fmaxf(sacc[ni][0], sacc[ni][1]));
            mloc[1] = fmaxf(mloc[1], fmaxf(sacc[ni][2], sacc[ni][3]));
        }
        #pragma unroll
        for (int r = 0; r < 2; r++) {
            mloc[r] = fmaxf(mloc[r], __shfl_xor_sync(0xffffffffu, mloc[r], 1));
            mloc[r] = fmaxf(mloc[r], __shfl_xor_sync(0xffffffffu, mloc[r], 2));
        }
        if (t == 0) {
            red_max[kw][qw][g    ] = mloc[0];
            red_max[kw][qw][g + 8] = mloc[1];
        }
        __syncthreads();
        float mn[2], alpha[2];
        #pragma unroll
        for (int r = 0; r < 2; r++) {
            int row = g + r * 8;
            float mk = fmaxf(red_max[0][qw][row], red_max[1][qw][row]);
            mn[r] = fmaxf(mi2[r], mk);
            alpha[r] = expq(mi2[r] - mn[r]);
            mi2[r] = mn[r];
        }
        float rs[2] = {0.f, 0.f};
        #pragma unroll
        for (int ni = 0; ni < 4; ni++) {
            #pragma unroll
            for (int j = 0; j < 4; j++) {
                int r = j >> 1;
                float p = expq(sacc[ni][j] - mn[r]);
                sacc[ni][j] = p;
                rs[r] += p;
            }
        }
        #pragma unroll
        for (int r = 0; r < 2; r++) {
            rs[r] += __shfl_xor_sync(0xffffffffu, rs[r], 1);
            rs[r] += __shfl_xor_sync(0xffffffffu, rs[r], 2);
        }
        if (t == 0) {
            red_sum[kw][qw][g    ] = rs[0];
            red_sum[kw][qw][g + 8] = rs[1];
        }
        #pragma unroll
        for (int ni = 0; ni < 4; ni++) {
            #pragma unroll
            for (int r = 0; r < 2; r++) {
                int row = qcol + g + r * 8;
                int col = kcol + ni * 8 + 2 * t;
                *(float2*)&Ps[row][col] = make_float2(sacc[ni][2 * r], sacc[ni][2 * r + 1]);
            }
        }
        if (kt + 1 < 16) {
            asm volatile("cp.async.wait_group 1;" ::: "memory");
        } else {
            asm volatile("cp.async.wait_group 0;" ::: "memory");
        }
        __syncthreads();

        #pragma unroll
        for (int r = 0; r < 2; r++) {
            int row = g + r * 8;
            float rstot = red_sum[0][qw][row] + red_sum[1][qw][row];
            li2[r] = li2[r] * alpha[r] + rstot;
        }
        #pragma unroll
        for (int ni = 0; ni < 4; ni++) {
            oacc[ni][0] *= alpha[0]; oacc[ni][1] *= alpha[0];
            oacc[ni][2] *= alpha[1]; oacc[ni][3] *= alpha[1];
        }

        #pragma unroll
        for (int kk = 0; kk < 64; kk += 8) {
            float a0 = Ps[qcol + g    ][kk + t    ];
            float a1 = Ps[qcol + g + 8][kk + t    ];
            float a2 = Ps[qcol + g    ][kk + t + 4];
            float a3 = Ps[qcol + g + 8][kk + t + 4];
            float ah0 = to_tf32(a0), ah1 = to_tf32(a1);
            float ah2 = to_tf32(a2), ah3 = to_tf32(a3);
            unsigned ah[4] = {__float_as_uint(ah0), __float_as_uint(ah1),
                              __float_as_uint(ah2), __float_as_uint(ah3)};
            unsigned al[4] = {__float_as_uint(a0 - ah0), __float_as_uint(a1 - ah1),
                              __float_as_uint(a2 - ah2), __float_as_uint(a3 - ah3)};
            #pragma unroll
            for (int ni = 0; ni < 4; ni++) {
                int c = kcol + ni * 8 + g;
                float b0 = Vs[c][kk + t    ];
                float b1 = Vs[c][kk + t + 4];
                float h0 = to_tf32(b0), h1 = to_tf32(b1);
                unsigned bh2[2] = {__float_as_uint(h0), __float_as_uint(h1)};
                unsigned bl2[2] = {__float_as_uint(b0 - h0), __float_as_uint(b1 - h1)};
                MMA_TF32(oacc[ni], ah, bl2);
                MMA_TF32(oacc[ni], al, bh2);
                MMA_TF32(oacc[ni], ah, bh2);
            }
        }

        __syncthreads();
        if (kt + 1 < 16) {
            int m1 = (kt + 1) << 6;
            for (int e = tid; e < 1024; e += 256) {
                int d  = e >> 4;
                int c4 = (e & 15) << 2;
                cpa16(&Vs[d][c4], vp + (size_t)(d * 4 + h) * NN + m1 + c4);
            }
            asm volatile("cp.async.commit_group;" ::: "memory");
        }
    }

    float inv[2] = {1.f / li2[0], 1.f / li2[1]};
    #pragma unroll
    for (int ni = 0; ni < 4; ni++) {
        #pragma unroll
        for (int j = 0; j < 4; j++) {
            int r = j >> 1;
            int row_q = qcol + g + r * 8;
            int col_d = kcol + ni * 8 + 2 * t + (j & 1);
            Ps[col_d][row_q] = oacc[ni][j] * inv[r];
        }
    }
    __syncthreads();
    for (int e = tid; e < 4096; e += 256) {
        int qi = e & 63, d = e >> 6;
        mp[(size_t)(d * 4 + h) * NN + q0 + qi] = Ps[d][qi];
    }
}

// ---------------------------------------------------------------------------
// BatchNorm stats (unchanged).
// ---------------------------------------------------------------------------
__global__ __launch_bounds__(256) void bn_stats_kernel(const float* __restrict__ g1,
                                                       const float* __restrict__ be1) {
    const int c = blockIdx.x;
    const int s = blockIdx.y;
    const float* hp = g_h + (size_t)s * HTEN;
    int tid = threadIdx.x;
    float sum = 0.f, sq = 0.f;
    for (int idx = tid; idx < 2048; idx += 256) {
        int b2 = idx >> 10, n = idx & 1023;
        float v = hp[((size_t)b2 * 512 + c) * NN + n];
        sum += v;
        sq = fmaf(v, v, sq);
    }
    #pragma unroll
    for (int w = 16; w; w >>= 1) {
        sum += __shfl_xor_sync(0xffffffffu, sum, w);
        sq  += __shfl_xor_sync(0xffffffffu, sq,  w);
    }
    __shared__ float ssum[8], ssq[8];
    int wid = tid >> 5, lane = tid & 31;
    if (lane == 0) { ssum[wid] = sum; ssq[wid] = sq; }
    __syncthreads();
    if (tid == 0) {
        float S = 0.f, Q = 0.f;
        #pragma unroll
        for (int i = 0; i < 8; i++) { S += ssum[i]; Q += ssq[i]; }
        float mean = S * (1.f / 2048.f);
        float var  = Q * (1.f / 2048.f) - mean * mean;
        float rstd = rsqrtf(var + 1e-5f);
        float sc = rstd * g1[c];
        float sh = be1[c] - mean * sc;
        g_stats[(s * 512 + c) * 2 + 0] = sc;
        g_stats[(s * 512 + c) * 2 + 1] = sh;
    }
}

// ---------------------------------------------------------------------------
// Host orchestration
// ---------------------------------------------------------------------------
extern "C" void kernel_launch(void* const* d_in, const int* in_sizes, int n_in,
                              void* d_out, int out_size) {
    const float* desc0 = (const float*)d_in[0];
    const float* desc1 = (const float*)d_in[1];
    const float* Wq  = (const float*)d_in[2];
    const float* bq  = (const float*)d_in[3];
    const float* Wk  = (const float*)d_in[4];
    const float* bk  = (const float*)d_in[5];
    const float* Wv  = (const float*)d_in[6];
    const float* bv  = (const float*)d_in[7];
    const float* Wm  = (const float*)d_in[8];
    const float* bm  = (const float*)d_in[9];
    const float* W1  = (const float*)d_in[10];
    const float* b1  = (const float*)d_in[11];
    const float* g1  = (const float*)d_in[12];
    const float* be1 = (const float*)d_in[13];
    const float* W2  = (const float*)d_in[14];
    const float* b2  = (const float*)d_in[15];
    float* out = (float*)d_out;

    float *qb, *kb, *vb, *msgb, *hb, *statsb, *whi, *wlo, *b1effb;
    cudaGetSymbolAddress((void**)&qb,    g_q);
    cudaGetSymbolAddress((void**)&kb,    g_k);
    cudaGetSymbolAddress((void**)&vb,    g_v);
    cudaGetSymbolAddress((void**)&msgb,  g_msg);
    cudaGetSymbolAddress((void**)&hb,    g_h);
    cudaGetSymbolAddress((void**)&statsb, g_stats);
    cudaGetSymbolAddress((void**)&whi,   g_whi);
    cudaGetSymbolAddress((void**)&wlo,   g_wlo);
    cudaGetSymbolAddress((void**)&b1effb, g_b1eff);

    cudaFuncSetAttribute(attn_kernel,
                         cudaFuncAttributeMaxDynamicSharedMemorySize, ATTN_SMEM);
    cudaFuncSetAttribute(gemm_tc,
                         cudaFuncAttributeMaxDynamicSharedMemorySize, GEMM_SMEM);

    presplit_kernel<<<(int)((TOTW / 4 + 255) / 256), 256>>>(Wq, Wk, Wv, Wm, W1, W2);
    // overwrite W1 cols 256:512 with split(W1[:,256:] @ Wm); stream order wins
    fuse_w1m_kernel<<<dim3(4, 8, 18), 128>>>(W1, Wm);
    b1eff_kernel<<<18, 512>>>(W1, b1, bm);

    cudaMemcpyAsync(out + 2 * (size_t)TEN, desc0, TEN * sizeof(float),
                    cudaMemcpyDeviceToDevice, 0);
    cudaMemcpyAsync(out + 3 * (size_t)TEN, desc1, TEN * sizeof(float),
                    cudaMemcpyDeviceToDevice, 0);

    const float* xa = desc0;
    const float* xb = desc1;

    for (int i = 0; i < 18; i++) {
        const float *sa, *sb, *ra, *rb;
        float *oa, *ob;
        if (i == 0) {
            sa = xa; sb = xb; ra = desc0; rb = desc1;
            oa = out;            ob = out + (size_t)TEN;
        } else if (i == 1) {
            sa = xb; sb = xa; ra = desc0; rb = desc1;
            oa = out + 4 * (size_t)TEN; ob = out + 5 * (size_t)TEN;
        } else {
            if ((i & 1) == 0) { sa = xa; sb = xb; }
            else              { sa = xb; sb = xa; }
            ra = xa; rb = xb;
            oa = out + (size_t)(2 + 2 * i) * TEN;
            ob = oa + (size_t)TEN;
        }

        const float* Wq_hi = whi + OFF_WQ + (size_t)i * 65536;
        const float* Wq_lo = wlo + OFF_WQ + (size_t)i * 65536;
        const float* Wk_hi = whi + OFF_WK + (size_t)i * 65536;
        const float* Wk_lo = wlo + OFF_WK + (size_t)i * 65536;
        const float* Wv_hi = whi + OFF_WV + (size_t)i * 65536;
        const float* Wv_lo = wlo + OFF_WV + (size_t)i * 65536;
        const float* W1_hi = whi + OFF_W1 + (size_t)i * 262144;
        const float* W1_lo = wlo + OFF_W1 + (size_t)i * 262144;
        const float* W2_hi = whi + OFF_W2 + (size_t)i * 131072;
        const float* W2_lo = wlo + OFF_W2 + (size_t)i * 131072;
        const float* bq_i = bq + (size_t)i * 256;
        const float* bk_i = bk + (size_t)i * 256;
        const float* bv_i = bv + (size_t)i * 256;
        const float* b1e_i = b1effb + (size_t)i * 512;
        const float* b2_i = b2 + (size_t)i * 256;
        const float* g1_i = g1 + (size_t)i * 512;
        const float* be_i = be1 + (size_t)i * 512;

        GArgs ga = {};
        ga.bnp[0] = statsb; ga.bnp[1] = statsb + 1024;

        // q/k/v merged
        ga.Whi[0] = Wq_hi; ga.Wlo[0] = Wq_lo; ga.bias[0] = bq_i;
        ga.Whi[1] = Wk_hi; ga.Wlo[1] = Wk_lo; ga.bias[1] = bk_i;
        ga.Whi[2] = Wv_hi; ga.Wlo[2] = Wv_lo; ga.bias[2] = bv_i;
        ga.X0[0][0] = xa; ga.X0[0][1] = xb;
        ga.X0[1][0] = sa; ga.X0[1][1] = sb;
        ga.X0[2][0] = sa; ga.X0[2][1] = sb;
        ga.out[0][0] = qb; ga.out[0][1] = qb + TEN;
        ga.out[1][0] = kb; ga.out[1][1] = kb + TEN;
        ga.out[2][0] = vb; ga.out[2][1] = vb + TEN;
        ga.X1[0] = ga.X1[1] = nullptr;
        ga.res[0] = ga.res[1] = nullptr;
        ga.M = 256; ga.K = 256; ga.K0 = 256; ga.use_bn = 0; ga.mtiles = 4;
        gemm_tc<<<dim3(32, 12, 2), 128, GEMM_SMEM>>>(ga);

        // attention -> g_msg
        attn_kernel<<<dim3(16, 8, 2), 256, ATTN_SMEM>>>();

        // h = [W1a | W1b*Wm] [x; attnout] + b1eff   (Wm GEMM eliminated)
        ga.Whi[0] = W1_hi; ga.Wlo[0] = W1_lo; ga.bias[0] = b1e_i;
        ga.X0[0][0] = xa; ga.X0[0][1] = xb;
        ga.X1[0] = msgb; ga.X1[1] = msgb + TEN;
        ga.out[0][0] = hb; ga.out[0][1] = hb + HTEN;
        ga.M = 512; ga.K = 512; ga.K0 = 256; ga.use_bn = 0; ga.mtiles = 8;
        gemm_tc<<<dim3(32, 8, 2), 128, GEMM_SMEM>>>(ga);

        // BN stats
        bn_stats_kernel<<<dim3(512, 2), 256>>>(g1_i, be_i);

        // out = res + W2 relu(BN(h)) + b2
        ga.Whi[0] = W2_hi; ga.Wlo[0] = W2_lo; ga.bias[0] = b2_i;
        ga.X0[0][0] = hb; ga.X0[0][1] = hb + HTEN;
        ga.X1[0] = ga.X1[1] = nullptr;
        ga.res[0] = ra; ga.res[1] = rb;
        ga.out[0][0] = oa; ga.out[0][1] = ob;
        ga.M = 256; ga.K = 512; ga.K0 = 512; ga.use_bn = 1; ga.mtiles = 4;
        gemm_tc<<<dim3(32, 4, 2), 128, GEMM_SMEM>>>(ga);
        ga.res[0] = ga.res[1] = nullptr;

        xa = oa; xb = ob;
    }
}

// round 15
// speedup vs baseline: 1.1495x; 1.0045x over previous
#include <cuda_runtime.h>
#include <math.h>

// ---------------------------------------------------------------------------
// AttentionalGNN: L=18 layers, D=256, H=4 (head dim 64), B=2, N=1024.
// Activations: [b2][C][N] fp32, channel c = d*4 + h.
// Round 15: BN stat collection fused into the W1 GEMM epilogue (deterministic
// per-block partials -> tiny bn_finalize). bn_stats full-pass kernel removed.
// GEMM/attention = round-14 winning config (Wm folded into W1).
// ---------------------------------------------------------------------------

#define BB   2
#define DD   256
#define NN   1024
#define TEN  (BB*DD*NN)
#define HTEN (BB*512*NN)

// Scratch (device globals). [stream][b2][C][N]
__device__ float g_q  [2*TEN];
__device__ float g_k  [2*TEN];
__device__ float g_v  [2*TEN];
__device__ float g_msg[2*TEN];
__device__ float g_h  [2*HTEN];
__device__ float g_stats[2*512*2];
__device__ float g_b1eff[18*512];
__device__ float g_bnpart[2*512*64*2];   // [s][m][partial(64)][sum,sumsq]

// Pre-split weights (hi/lo), concatenated: Wq|Wk|Wv|Wm|W1|W2
#define SZ_D  (18L*256*256)
#define SZ_1  (18L*512*512)
#define SZ_2  (18L*256*512)
#define OFF_WQ 0L
#define OFF_WK (SZ_D)
#define OFF_WV (2*SZ_D)
#define OFF_WM (3*SZ_D)
#define OFF_W1 (4*SZ_D)
#define OFF_W2 (4*SZ_D + SZ_1)
#define TOTW   (4*SZ_D + SZ_1 + SZ_2)
__device__ float g_whi[TOTW];
__device__ float g_wlo[TOTW];

__device__ __forceinline__ float to_tf32(float x) {
    unsigned u;
    asm("cvt.rna.tf32.f32 %0, %1;" : "=r"(u) : "f"(x));
    return __uint_as_float(u);
}

#define MMA_TF32(acc, af, bf)                                                  \
    asm volatile(                                                              \
        "mma.sync.aligned.m16n8k8.row.col.f32.tf32.tf32.f32 "                  \
        "{%0,%1,%2,%3}, {%4,%5,%6,%7}, {%8,%9}, {%0,%1,%2,%3};"                \
        : "+f"(acc[0]), "+f"(acc[1]), "+f"(acc[2]), "+f"(acc[3])               \
        : "r"(af[0]), "r"(af[1]), "r"(af[2]), "r"(af[3]),                      \
          "r"(bf[0]), "r"(bf[1]))

__device__ __forceinline__ void cpa16(float* dst, const float* src) {
    unsigned sa = (unsigned)__cvta_generic_to_shared(dst);
    asm volatile("cp.async.ca.shared.global [%0], [%1], 16;" :: "r"(sa), "l"(src));
}

// exp on the FMA pipe: round-to-int trick + 2^f poly (deg 6), rel err ~2e-7.
__device__ __forceinline__ float expq(float x) {
    x = fmaxf(x, -80.f);
    float t = fmaf(x, 1.4426950408889634f, 12582912.f);
    float n = t - 12582912.f;
    float f = fmaf(x, 1.4426950408889634f, -n);
    float p = 0.0001540353039338161f;
    p = fmaf(p, f, 0.0013333558146428443f);
    p = fmaf(p, f, 0.009618129107628477f);
    p = fmaf(p, f, 0.05550410866482158f);
    p = fmaf(p, f, 0.2402265069591007f);
    p = fmaf(p, f, 0.6931471805599453f);
    p = fmaf(p, f, 1.0f);
    int ni = __float_as_int(t) - 0x4B400000;
    return __int_as_float(__float_as_int(p) + (ni << 23));
}

// ---------------------------------------------------------------------------
// Weight pre-split
// ---------------------------------------------------------------------------
__global__ __launch_bounds__(256) void presplit_kernel(
    const float* __restrict__ Wq, const float* __restrict__ Wk,
    const float* __restrict__ Wv, const float* __restrict__ Wm,
    const float* __restrict__ W1, const float* __restrict__ W2) {
    long i = ((long)blockIdx.x * 256 + threadIdx.x) * 4;
    if (i >= TOTW) return;
    const float* src; long off = i;
    if      (i < OFF_WK) { src = Wq; }
    else if (i < OFF_WV) { src = Wk; off = i - OFF_WK; }
    else if (i < OFF_WM) { src = Wv; off = i - OFF_WV; }
    else if (i < OFF_W1) { src = Wm; off = i - OFF_WM; }
    else if (i < OFF_W2) { src = W1; off = i - OFF_W1; }
    else                 { src = W2; off = i - OFF_W2; }
    float4 w = *(const float4*)(src + off);
    float4 h, l;
    h.x = to_tf32(w.x); l.x = w.x - h.x;
    h.y = to_tf32(w.y); l.y = w.y - h.y;
    h.z = to_tf32(w.z); l.z = w.z - h.z;
    h.w = to_tf32(w.w); l.w = w.w - h.w;
    *(float4*)(g_whi + i) = h;
    *(float4*)(g_wlo + i) = l;
}

// ---------------------------------------------------------------------------
// W1m precompute: W1m[m][i] = sum_o W1[m][256+o]*Wm[o][i], split into the
// W1 weight slot cols 256:512. Runs AFTER presplit (stream order wins).
// ---------------------------------------------------------------------------
__global__ __launch_bounds__(128) void fuse_w1m_kernel(
    const float* __restrict__ W1, const float* __restrict__ Wm) {
    __shared__ float Ah[64][36], Al[64][36];
    __shared__ float Bh[32][68], Bl[32][68];
    const int layer = blockIdx.z;
    const int n0 = blockIdx.x << 6;
    const int m0 = blockIdx.y << 6;
    const float* W1p = W1 + (size_t)layer * 262144;
    const float* Wmp = Wm + (size_t)layer * 65536;
    const int tid = threadIdx.x;
    const int warp = tid >> 5, lane = tid & 31;
    const int wm = (warp >> 1) << 5;
    const int wn = (warp & 1) << 5;
    const int g = lane >> 2, t = lane & 3;

    float acc[2][4][4];
    #pragma unroll
    for (int mi = 0; mi < 2; mi++)
        #pragma unroll
        for (int ni = 0; ni < 4; ni++)
            #pragma unroll
            for (int r = 0; r < 4; r++) acc[mi][ni][r] = 0.f;

    for (int k0 = 0; k0 < 256; k0 += 32) {
        #pragma unroll
        for (int e = tid; e < 512; e += 128) {
            int m  = e >> 3;
            int kq = (e & 7) << 2;
            float4 w = *(const float4*)&W1p[(size_t)(m0 + m) * 512 + 256 + k0 + kq];
            float wa[4] = {w.x, w.y, w.z, w.w};
            #pragma unroll
            for (int q = 0; q < 4; q++) {
                float hi = to_tf32(wa[q]);
                Ah[m][kq + q] = hi;
                Al[m][kq + q] = wa[q] - hi;
            }
        }
        #pragma unroll
        for (int e = tid; e < 512; e += 128) {
            int kk = e >> 4;
            int nq = (e & 15) << 2;
            float4 v = *(const float4*)&Wmp[(size_t)(k0 + kk) * 256 + n0 + nq];
            float va[4] = {v.x, v.y, v.z, v.w};
            #pragma unroll
            for (int q = 0; q < 4; q++) {
                float hi = to_tf32(va[q]);
                Bh[kk][nq + q] = hi;
                Bl[kk][nq + q] = va[q] - hi;
            }
        }
        __syncthreads();
        #pragma unroll
        for (int kk = 0; kk < 32; kk += 8) {
            unsigned afh[2][4], afl[2][4];
            #pragma unroll
            for (int mi = 0; mi < 2; mi++) {
                int r0 = wm + mi * 16 + g;
                afh[mi][0] = __float_as_uint(Ah[r0    ][kk + t    ]);
                afh[mi][1] = __float_as_uint(Ah[r0 + 8][kk + t    ]);
                afh[mi][2] = __float_as_uint(Ah[r0    ][kk + t + 4]);
                afh[mi][3] = __float_as_uint(Ah[r0 + 8][kk + t + 4]);
                afl[mi][0] = __float_as_uint(Al[r0    ][kk + t    ]);
                afl[mi][1] = __float_as_uint(Al[r0 + 8][kk + t    ]);
                afl[mi][2] = __float_as_uint(Al[r0    ][kk + t + 4]);
                afl[mi][3] = __float_as_uint(Al[r0 + 8][kk + t + 4]);
            }
            #pragma unroll
            for (int ni = 0; ni < 4; ni++) {
                int c = wn + ni * 8 + g;
                unsigned bh2[2] = {__float_as_uint(Bh[kk + t][c]),
                                   __float_as_uint(Bh[kk + t + 4][c])};
                unsigned bl2[2] = {__float_as_uint(Bl[kk + t][c]),
                                   __float_as_uint(Bl[kk + t + 4][c])};
                #pragma unroll
                for (int mi = 0; mi < 2; mi++) {
                    MMA_TF32(acc[mi][ni], afh[mi], bl2);
                    MMA_TF32(acc[mi][ni], afl[mi], bh2);
                    MMA_TF32(acc[mi][ni], afh[mi], bh2);
                }
            }
        }
        __syncthreads();
    }

    size_t base = OFF_W1 + (size_t)layer * 262144;
    #pragma unroll
    for (int mi = 0; mi < 2; mi++) {
        #pragma unroll
        for (int half = 0; half < 2; half++) {
            int m = m0 + wm + mi * 16 + g + half * 8;
            #pragma unroll
            for (int ni = 0; ni < 4; ni++) {
                int col = n0 + wn + ni * 8 + 2 * t;
                size_t off = base + (size_t)m * 512 + 256 + col;
                float v0 = acc[mi][ni][2 * half + 0];
                float v1 = acc[mi][ni][2 * half + 1];
                float h0 = to_tf32(v0), h1 = to_tf32(v1);
                *(float2*)(g_whi + off) = make_float2(h0, h1);
                *(float2*)(g_wlo + off) = make_float2(v0 - h0, v1 - h1);
            }
        }
    }
}

// b1eff[l][m] = b1[l][m] + sum_o W1[l][m][256+o] * bm[l][o]
__global__ __launch_bounds__(512) void b1eff_kernel(
    const float* __restrict__ W1, const float* __restrict__ b1,
    const float* __restrict__ bm) {
    int layer = blockIdx.x;
    int m = threadIdx.x;
    const float* w = W1 + (size_t)layer * 262144 + (size_t)m * 512 + 256;
    const float* bmp = bm + layer * 256;
    float s = b1[layer * 512 + m];
    for (int o = 0; o < 256; o++) s = fmaf(w[o], bmp[o], s);
    g_b1eff[layer * 512 + m] = s;
}

// ---------------------------------------------------------------------------
// Tensor-core GEMM (3xTF32), 2-stage cp.async pipeline, 128 threads.
// bn_emit: epilogue also reduces per-row (sum, sumsq) of the output tile into
// g_bnpart (deterministic: every slot written each layer, fixed tree).
// ---------------------------------------------------------------------------
struct GArgs {
    const float* Whi[3];
    const float* Wlo[3];
    const float* bias[3];
    const float* X0[3][2];
    const float* X1[2];
    const float* res[2];
    const float* bnp[2];
    float*       out[3][2];
    int M, K, K0, use_bn, mtiles, bn_emit;
};

#define GEMM_SMEM (13696 * 4)

__global__ __launch_bounds__(128) void gemm_tc(GArgs a) {
    extern __shared__ __align__(16) float smem[];
    // offsets (floats):  AH: 0 (2x2304) | AL: 4608 | BS: 9216 (2x2176) | BN: 13568 (2x64)

    const int s   = blockIdx.z;
    const int jt  = blockIdx.x;
    const int b2  = jt >> 4;
    const int n0  = (jt & 15) << 6;
    const int mat = blockIdx.y / a.mtiles;
    const int m0  = (blockIdx.y % a.mtiles) << 6;
    const int tid = threadIdx.x;
    const int warp = tid >> 5, lane = tid & 31;
    const int wm = (warp >> 1) << 5;
    const int wn = (warp & 1) << 5;
    const int g = lane >> 2, t = lane & 3;

    const int K = a.K, K0 = a.K0, M = a.M;
    const int use_bn = a.use_bn;
    const float* __restrict__ Whi = a.Whi[mat];
    const float* __restrict__ Wlo = a.Wlo[mat];
    const float* __restrict__ X0  = a.X0[mat][s];
    const float* __restrict__ X1  = a.X1[s];
    const float* __restrict__ bnp = a.bnp[s];

    float acc[2][4][4];
    #pragma unroll
    for (int mi = 0; mi < 2; mi++)
        #pragma unroll
        for (int ni = 0; ni < 4; ni++)
            #pragma unroll
            for (int r = 0; r < 4; r++) acc[mi][ni][r] = 0.f;

    auto load_tile = [&](int k0, int buf) {
        float* AHb = smem + buf * 2304;
        float* ALb = smem + 4608 + buf * 2304;
        float* BSb = smem + 9216 + buf * 2176;
        float* BNb = smem + 13568 + buf * 64;
        #pragma unroll
        for (int e = tid; e < 512; e += 128) {
            int m  = e >> 3;
            int kq = (e & 7) << 2;
            size_t woff = (size_t)(m0 + m) * K + k0 + kq;
            cpa16(AHb + m * 36 + kq, Whi + woff);
            cpa16(ALb + m * 36 + kq, Wlo + woff);
        }
        #pragma unroll
        for (int e = tid; e < 512; e += 128) {
            int kk = e >> 4;
            int nq = (e & 15) << 2;
            int k = k0 + kk;
            const float* src = (k < K0)
                ? X0 + ((size_t)b2 * K0 + k) * NN + n0 + nq
                : X1 + ((size_t)b2 * (K - K0) + (k - K0)) * NN + n0 + nq;
            cpa16(BSb + kk * 68 + nq, src);
        }
        if (use_bn && tid < 64) BNb[tid] = bnp[2 * k0 + tid];
        asm volatile("cp.async.commit_group;" ::: "memory");
    };

    const int niter = K >> 5;
    load_tile(0, 0);

    for (int it = 0; it < niter; it++) {
        const int buf = it & 1;
        if (it + 1 < niter) {
            load_tile((it + 1) << 5, buf ^ 1);
            asm volatile("cp.async.wait_group 1;" ::: "memory");
        } else {
            asm volatile("cp.async.wait_group 0;" ::: "memory");
        }
        __syncthreads();

        const float* AHb = smem + buf * 2304;
        const float* ALb = smem + 4608 + buf * 2304;
        const float* BSb = smem + 9216 + buf * 2176;
        const float* BNb = smem + 13568 + buf * 64;

        #pragma unroll
        for (int kk = 0; kk < 32; kk += 8) {
            unsigned afh[2][4], afl[2][4];
            #pragma unroll
            for (int mi = 0; mi < 2; mi++) {
                int r0 = wm + mi * 16 + g;
                afh[mi][0] = __float_as_uint(AHb[(r0    ) * 36 + kk + t    ]);
                afh[mi][1] = __float_as_uint(AHb[(r0 + 8) * 36 + kk + t    ]);
                afh[mi][2] = __float_as_uint(AHb[(r0    ) * 36 + kk + t + 4]);
                afh[mi][3] = __float_as_uint(AHb[(r0 + 8) * 36 + kk + t + 4]);
                afl[mi][0] = __float_as_uint(ALb[(r0    ) * 36 + kk + t    ]);
                afl[mi][1] = __float_as_uint(ALb[(r0 + 8) * 36 + kk + t    ]);
                afl[mi][2] = __float_as_uint(ALb[(r0    ) * 36 + kk + t + 4]);
                afl[mi][3] = __float_as_uint(ALb[(r0 + 8) * 36 + kk + t + 4]);
            }
            float sc0 = 1.f, sh0 = 0.f, sc1 = 1.f, sh1 = 0.f;
            if (use_bn) {
                sc0 = BNb[2 * (kk + t)];     sh0 = BNb[2 * (kk + t) + 1];
                sc1 = BNb[2 * (kk + t + 4)]; sh1 = BNb[2 * (kk + t + 4) + 1];
            }
            #pragma unroll
            for (int ni = 0; ni < 4; ni++) {
                int c = wn + ni * 8 + g;
                float b0 = BSb[(kk + t    ) * 68 + c];
                float b1 = BSb[(kk + t + 4) * 68 + c];
                if (use_bn) {
                    b0 = fmaxf(fmaf(b0, sc0, sh0), 0.f);
                    b1 = fmaxf(fmaf(b1, sc1, sh1), 0.f);
                }
                float h0 = to_tf32(b0), h1 = to_tf32(b1);
                unsigned bh2[2] = {__float_as_uint(h0), __float_as_uint(h1)};
                unsigned bl2[2] = {__float_as_uint(b0 - h0), __float_as_uint(b1 - h1)};
                #pragma unroll
                for (int mi = 0; mi < 2; mi++) {
                    MMA_TF32(acc[mi][ni], afh[mi], bl2);
                    MMA_TF32(acc[mi][ni], afl[mi], bh2);
                    MMA_TF32(acc[mi][ni], afh[mi], bh2);
                }
            }
        }
        __syncthreads();
    }

    const float* resp = a.res[s];
    const float* biasp = a.bias[mat];
    float* outp = a.out[mat][s];
    float rsum[2][2] = {}, rsq[2][2] = {};
    #pragma unroll
    for (int mi = 0; mi < 2; mi++) {
        #pragma unroll
        for (int half = 0; half < 2; half++) {
            int m = m0 + wm + mi * 16 + g + half * 8;
            float bb = biasp[m];
            #pragma unroll
            for (int ni = 0; ni < 4; ni++) {
                int col = n0 + wn + ni * 8 + 2 * t;
                size_t off = ((size_t)b2 * M + m) * NN + col;
                float2 c;
                c.x = acc[mi][ni][2 * half + 0] + bb;
                c.y = acc[mi][ni][2 * half + 1] + bb;
                if (resp) {
                    float2 r = *(const float2*)(resp + off);
                    c.x += r.x; c.y += r.y;
                }
                *(float2*)(outp + off) = c;
                if (a.bn_emit) {
                    rsum[mi][half] += c.x + c.y;
                    rsq[mi][half] = fmaf(c.x, c.x, fmaf(c.y, c.y, rsq[mi][half]));
                }
            }
        }
    }
    if (a.bn_emit) {
        #pragma unroll
        for (int mi = 0; mi < 2; mi++)
            #pragma unroll
            for (int half = 0; half < 2; half++) {
                float s1 = rsum[mi][half], s2 = rsq[mi][half];
                s1 += __shfl_xor_sync(0xffffffffu, s1, 1);
                s2 += __shfl_xor_sync(0xffffffffu, s2, 1);
                s1 += __shfl_xor_sync(0xffffffffu, s1, 2);
                s2 += __shfl_xor_sync(0xffffffffu, s2, 2);
                if (t == 0) {
                    int m = m0 + wm + mi * 16 + g + half * 8;
                    int p = jt * 2 + (warp & 1);
                    *(float2*)&g_bnpart[(((size_t)s * 512 + m) * 64 + p) * 2] =
                        make_float2(s1, s2);
                }
            }
    }
}

// ---------------------------------------------------------------------------
// BN finalize: sum 64 deterministic partials per (stream, channel).
// grid = (512, 2), 64 threads.
// ---------------------------------------------------------------------------
__global__ __launch_bounds__(64) void bn_finalize_kernel(
    const float* __restrict__ g1, const float* __restrict__ be1) {
    const int c = blockIdx.x;
    const int s = blockIdx.y;
    const int tid = threadIdx.x;
    float2 v = *(const float2*)&g_bnpart[(((size_t)s * 512 + c) * 64 + tid) * 2];
    float S = v.x, Q = v.y;
    #pragma unroll
    for (int w = 16; w; w >>= 1) {
        S += __shfl_xor_sync(0xffffffffu, S, w);
        Q += __shfl_xor_sync(0xffffffffu, Q, w);
    }
    __shared__ float sS[2], sQ[2];
    if ((tid & 31) == 0) { sS[tid >> 5] = S; sQ[tid >> 5] = Q; }
    __syncthreads();
    if (tid == 0) {
        S = sS[0] + sS[1];
        Q = sQ[0] + sQ[1];
        float mean = S * (1.f / 2048.f);
        float var  = Q * (1.f / 2048.f) - mean * mean;
        float rstd = rsqrtf(var + 1e-5f);
        float sc = rstd * g1[c];
        float sh = be1[c] - mean * sc;
        g_stats[(s * 512 + c) * 2 + 0] = sc;
        g_stats[(s * 512 + c) * 2 + 1] = sh;
    }
}

// ---------------------------------------------------------------------------
// Tensor-core flash attention (3xTF32), 64-q tiles, software-pipelined
// (round-12 version, unchanged).
// ---------------------------------------------------------------------------
#define ATTN_SMEM (6 * 64 * 68 * 4)

__global__ __launch_bounds__(256) void attn_kernel() {
    extern __shared__ __align__(16) float sm[];
    float (*Qh)[68]  = (float(*)[68])(sm);
    float (*Ql)[68]  = (float(*)[68])(sm + 4352);
    float (*Ks0)[68] = (float(*)[68])(sm + 2 * 4352);
    float (*Ks1)[68] = (float(*)[68])(sm + 3 * 4352);
    float (*Vs)[68]  = (float(*)[68])(sm + 4 * 4352);
    float (*Ps)[68]  = (float(*)[68])(sm + 5 * 4352);
    __shared__ float red_max[2][4][16];
    __shared__ float red_sum[2][4][16];

    const int qt = blockIdx.x;
    const int bh = blockIdx.y;
    const int s  = blockIdx.z;
    const int b2 = bh >> 2, h = bh & 3;
    const int q0 = qt << 6;
    const int tid = threadIdx.x;
    const int warp = tid >> 5, lane = tid & 31;
    const int g = lane >> 2, t = lane & 3;
    const int qw = warp >> 1, kw = warp & 1;
    const int qcol = qw << 4;
    const int kcol = kw << 5;

    size_t base = (size_t)s * TEN + (size_t)b2 * (DD * NN);
    const float* __restrict__ qp = g_q + base;
    const float* __restrict__ kp = g_k + base;
    const float* __restrict__ vp = g_v + base;
    float* mp = g_msg + base;

    for (int e = tid; e < 4096; e += 256) {
        int qi = e & 63, d = e >> 6;
        float v = qp[(size_t)(d * 4 + h) * NN + q0 + qi] * 0.125f;
        float hi = to_tf32(v);
        Qh[d][qi] = hi;
        Ql[d][qi] = v - hi;
    }

    for (int e = tid; e < 1024; e += 256) {
        int d  = e >> 4;
        int c4 = (e & 15) << 2;
        cpa16(&Ks0[d][c4], kp + (size_t)(d * 4 + h) * NN + c4);
    }
    asm volatile("cp.async.commit_group;" ::: "memory");
    for (int e = tid; e < 1024; e += 256) {
        int d  = e >> 4;
        int c4 = (e & 15) << 2;
        cpa16(&Vs[d][c4], vp + (size_t)(d * 4 + h) * NN + c4);
    }
    asm volatile("cp.async.commit_group;" ::: "memory");

    float oacc[4][4] = {};
    float mi2[2] = {-1e30f, -1e30f};
    float li2[2] = {0.f, 0.f};

    for (int kt = 0; kt < 16; kt++) {
        float (*Kb)[68] = (kt & 1) ? Ks1 : Ks0;
        float (*Kn)[68] = (kt & 1) ? Ks0 : Ks1;

        asm volatile("cp.async.wait_group 1;" ::: "memory");
        __syncthreads();

        if (kt + 1 < 16) {
            int m1 = (kt + 1) << 6;
            for (int e = tid; e < 1024; e += 256) {
                int d  = e >> 4;
                int c4 = (e & 15) << 2;
                cpa16(&Kn[d][c4], kp + (size_t)(d * 4 + h) * NN + m1 + c4);
            }
            asm volatile("cp.async.commit_group;" ::: "memory");
        }

        float sacc[4][4] = {};
        #pragma unroll
        for (int kk = 0; kk < 64; kk += 8) {
            unsigned ah[4], al[4];
            ah[0] = __float_as_uint(Qh[kk + t    ][qcol + g    ]);
            ah[1] = __float_as_uint(Qh[kk + t    ][qcol + g + 8]);
            ah[2] = __float_as_uint(Qh[kk + t + 4][qcol + g    ]);
            ah[3] = __float_as_uint(Qh[kk + t + 4][qcol + g + 8]);
            al[0] = __float_as_uint(Ql[kk + t    ][qcol + g    ]);
            al[1] = __float_as_uint(Ql[kk + t    ][qcol + g + 8]);
            al[2] = __float_as_uint(Ql[kk + t + 4][qcol + g    ]);
            al[3] = __float_as_uint(Ql[kk + t + 4][qcol + g + 8]);
            #pragma unroll
            for (int ni = 0; ni < 4; ni++) {
                int c = kcol + ni * 8 + g;
                float b0 = Kb[kk + t    ][c];
                float b1 = Kb[kk + t + 4][c];
                float h0 = to_tf32(b0), h1 = to_tf32(b1);
                unsigned bh2[2] = {__float_as_uint(h0), __float_as_uint(h1)};
                unsigned bl2[2] = {__float_as_uint(b0 - h0), __float_as_uint(b1 - h1)};
                MMA_TF32(sacc[ni], ah, bl2);
                MMA_TF32(sacc[ni], al, bh2);
                MMA_TF32(sacc[ni], ah, bh2);
            }
        }

        float mloc[2] = {-1e30f, -1e30f};
        #pragma unroll
        for (int ni = 0; ni < 4; ni++) {
            mloc[0] = fmaxf(mloc[0], fmaxf(sacc[ni][0], sacc[ni][1]));
            mloc[1] = fmaxf(mloc[1], fmaxf(sacc[ni][2], sacc[ni][3]));
        }
        #pragma unroll
        for (int r = 0; r < 2; r++) {
            mloc[r] = fmaxf(mloc[r], __shfl_xor_sync(0xffffffffu, mloc[r], 1));
            mloc[r] = fmaxf(mloc[r], __shfl_xor_sync(0xffffffffu, mloc[r], 2));
        }
        if (t == 0) {
            red_max[kw][qw][g    ] = mloc[0];
            red_max[kw][qw][g + 8] = mloc[1];
        }
        __syncthreads();
        float mn[2], alpha[2];
        #pragma unroll
        for (int r = 0; r < 2; r++) {
            int row = g + r * 8;
            float mk = fmaxf(red_max[0][qw][row], red_max[1][qw][row]);
            mn[r] = fmaxf(mi2[r], mk);
            alpha[r] = expq(mi2[r] - mn[r]);
            mi2[r] = mn[r];
        }
        float rs[2] = {0.f, 0.f};
        #pragma unroll
        for (int ni = 0; ni < 4; ni++) {
            #pragma unroll
            for (int j = 0; j < 4; j++) {
                int r = j >> 1;
                float p = expq(sacc[ni][j] - mn[r]);
                sacc[ni][j] = p;
                rs[r] += p;
            }
        }
        #pragma unroll
        for (int r = 0; r < 2; r++) {
            rs[r] += __shfl_xor_sync(0xffffffffu, rs[r], 1);
            rs[r] += __shfl_xor_sync(0xffffffffu, rs[r], 2);
        }
        if (t == 0) {
            red_sum[kw][qw][g    ] = rs[0];
            red_sum[kw][qw][g + 8] = rs[1];
        }
        #pragma unroll
        for (int ni = 0; ni < 4; ni++) {
            #pragma unroll
            for (int r = 0; r < 2; r++) {
                int row = qcol + g + r * 8;
                int col = kcol + ni * 8 + 2 * t;
                *(float2*)&Ps[row][col] = make_float2(sacc[ni][2 * r], sacc[ni][2 * r + 1]);
            }
        }
        if (kt + 1 < 16) {
            asm volatile("cp.async.wait_group 1;" ::: "memory");
        } else {
            asm volatile("cp.async.wait_group 0;" ::: "memory");
        }
        __syncthreads();

        #pragma unroll
        for (int r = 0; r < 2; r++) {
            int row = g + r * 8;
            float rstot = red_sum[0][qw][row] + red_sum[1][qw][row];
            li2[r] = li2[r] * alpha[r] + rstot;
        }
        #pragma unroll
        for (int ni = 0; ni < 4; ni++) {
            oacc[ni][0] *= alpha[0]; oacc[ni][1] *= alpha[0];
            oacc[ni][2] *= alpha[1]; oacc[ni][3] *= alpha[1];
        }

        #pragma unroll
        for (int kk = 0; kk < 64; kk += 8) {
            float a0 = Ps[qcol + g    ][kk + t    ];
            float a1 = Ps[qcol + g + 8][kk + t    ];
            float a2 = Ps[qcol + g    ][kk + t + 4];
            float a3 = Ps[qcol + g + 8][kk + t + 4];
            float ah0 = to_tf32(a0), ah1 = to_tf32(a1);
            float ah2 = to_tf32(a2), ah3 = to_tf32(a3);
            unsigned ah[4] = {__float_as_uint(ah0), __float_as_uint(ah1),
                              __float_as_uint(ah2), __float_as_uint(ah3)};
            unsigned al[4] = {__float_as_uint(a0 - ah0), __float_as_uint(a1 - ah1),
                              __float_as_uint(a2 - ah2), __float_as_uint(a3 - ah3)};
            #pragma unroll
            for (int ni = 0; ni < 4; ni++) {
                int c = kcol + ni * 8 + g;
                float b0 = Vs[c][kk + t    ];
                float b1 = Vs[c][kk + t + 4];
                float h0 = to_tf32(b0), h1 = to_tf32(b1);
                unsigned bh2[2] = {__float_as_uint(h0), __float_as_uint(h1)};
                unsigned bl2[2] = {__float_as_uint(b0 - h0), __float_as_uint(b1 - h1)};
                MMA_TF32(oacc[ni], ah, bl2);
                MMA_TF32(oacc[ni], al, bh2);
                MMA_TF32(oacc[ni], ah, bh2);
            }
        }

        __syncthreads();
        if (kt + 1 < 16) {
            int m1 = (kt + 1) << 6;
            for (int e = tid; e < 1024; e += 256) {
                int d  = e >> 4;
                int c4 = (e & 15) << 2;
                cpa16(&Vs[d][c4], vp + (size_t)(d * 4 + h) * NN + m1 + c4);
            }
            asm volatile("cp.async.commit_group;" ::: "memory");
        }
    }

    float inv[2] = {1.f / li2[0], 1.f / li2[1]};
    #pragma unroll
    for (int ni = 0; ni < 4; ni++) {
        #pragma unroll
        for (int j = 0; j < 4; j++) {
            int r = j >> 1;
            int row_q = qcol + g + r * 8;
            int col_d = kcol + ni * 8 + 2 * t + (j & 1);
            Ps[col_d][row_q] = oacc[ni][j] * inv[r];
        }
    }
    __syncthreads();
    for (int e = tid; e < 4096; e += 256) {
        int qi = e & 63, d = e >> 6;
        mp[(size_t)(d * 4 + h) * NN + q0 + qi] = Ps[d][qi];
    }
}

// ---------------------------------------------------------------------------
// Host orchestration
// ---------------------------------------------------------------------------
extern "C" void kernel_launch(void* const* d_in, const int* in_sizes, int n_in,
                              void* d_out, int out_size) {
    const float* desc0 = (const float*)d_in[0];
    const float* desc1 = (const float*)d_in[1];
    const float* Wq  = (const float*)d_in[2];
    const float* bq  = (const float*)d_in[3];
    const float* Wk  = (const float*)d_in[4];
    const float* bk  = (const float*)d_in[5];
    const float* Wv  = (const float*)d_in[6];
    const float* bv  = (const float*)d_in[7];
    const float* Wm  = (const float*)d_in[8];
    const float* bm  = (const float*)d_in[9];
    const float* W1  = (const float*)d_in[10];
    const float* b1  = (const float*)d_in[11];
    const float* g1  = (const float*)d_in[12];
    const float* be1 = (const float*)d_in[13];
    const float* W2  = (const float*)d_in[14];
    const float* b2  = (const float*)d_in[15];
    float* out = (float*)d_out;

    float *qb, *kb, *vb, *msgb, *hb, *statsb, *whi, *wlo, *b1effb;
    cudaGetSymbolAddress((void**)&qb,    g_q);
    cudaGetSymbolAddress((void**)&kb,    g_k);
    cudaGetSymbolAddress((void**)&vb,    g_v);
    cudaGetSymbolAddress((void**)&msgb,  g_msg);
    cudaGetSymbolAddress((void**)&hb,    g_h);
    cudaGetSymbolAddress((void**)&statsb, g_stats);
    cudaGetSymbolAddress((void**)&whi,   g_whi);
    cudaGetSymbolAddress((void**)&wlo,   g_wlo);
    cudaGetSymbolAddress((void**)&b1effb, g_b1eff);

    cudaFuncSetAttribute(attn_kernel,
                         cudaFuncAttributeMaxDynamicSharedMemorySize, ATTN_SMEM);
    cudaFuncSetAttribute(gemm_tc,
                         cudaFuncAttributeMaxDynamicSharedMemorySize, GEMM_SMEM);

    presplit_kernel<<<(int)((TOTW / 4 + 255) / 256), 256>>>(Wq, Wk, Wv, Wm, W1, W2);
    fuse_w1m_kernel<<<dim3(4, 8, 18), 128>>>(W1, Wm);
    b1eff_kernel<<<18, 512>>>(W1, b1, bm);

    cudaMemcpyAsync(out + 2 * (size_t)TEN, desc0, TEN * sizeof(float),
                    cudaMemcpyDeviceToDevice, 0);
    cudaMemcpyAsync(out + 3 * (size_t)TEN, desc1, TEN * sizeof(float),
                    cudaMemcpyDeviceToDevice, 0);

    const float* xa = desc0;
    const float* xb = desc1;

    for (int i = 0; i < 18; i++) {
        const float *sa, *sb, *ra, *rb;
        float *oa, *ob;
        if (i == 0) {
            sa = xa; sb = xb; ra = desc0; rb = desc1;
            oa = out;            ob = out + (size_t)TEN;
        } else if (i == 1) {
            sa = xb; sb = xa; ra = desc0; rb = desc1;
            oa = out + 4 * (size_t)TEN; ob = out + 5 * (size_t)TEN;
        } else {
            if ((i & 1) == 0) { sa = xa; sb = xb; }
            else              { sa = xb; sb = xa; }
            ra = xa; rb = xb;
            oa = out + (size_t)(2 + 2 * i) * TEN;
            ob = oa + (size_t)TEN;
        }

        const float* Wq_hi = whi + OFF_WQ + (size_t)i * 65536;
        const float* Wq_lo = wlo + OFF_WQ + (size_t)i * 65536;
        const float* Wk_hi = whi + OFF_WK + (size_t)i * 65536;
        const float* Wk_lo = wlo + OFF_WK + (size_t)i * 65536;
        const float* Wv_hi = whi + OFF_WV + (size_t)i * 65536;
        const float* Wv_lo = wlo + OFF_WV + (size_t)i * 65536;
        const float* W1_hi = whi + OFF_W1 + (size_t)i * 262144;
        const float* W1_lo = wlo + OFF_W1 + (size_t)i * 262144;
        const float* W2_hi = whi + OFF_W2 + (size_t)i * 131072;
        const float* W2_lo = wlo + OFF_W2 + (size_t)i * 131072;
        const float* bq_i = bq + (size_t)i * 256;
        const float* bk_i = bk + (size_t)i * 256;
        const float* bv_i = bv + (size_t)i * 256;
        const float* b1e_i = b1effb + (size_t)i * 512;
        const float* b2_i = b2 + (size_t)i * 256;
        const float* g1_i = g1 + (size_t)i * 512;
        const float* be_i = be1 + (size_t)i * 512;

        GArgs ga = {};
        ga.bnp[0] = statsb; ga.bnp[1] = statsb + 1024;

        // q/k/v merged
        ga.Whi[0] = Wq_hi; ga.Wlo[0] = Wq_lo; ga.bias[0] = bq_i;
        ga.Whi[1] = Wk_hi; ga.Wlo[1] = Wk_lo; ga.bias[1] = bk_i;
        ga.Whi[2] = Wv_hi; ga.Wlo[2] = Wv_lo; ga.bias[2] = bv_i;
        ga.X0[0][0] = xa; ga.X0[0][1] = xb;
        ga.X0[1][0] = sa; ga.X0[1][1] = sb;
        ga.X0[2][0] = sa; ga.X0[2][1] = sb;
        ga.out[0][0] = qb; ga.out[0][1] = qb + TEN;
        ga.out[1][0] = kb; ga.out[1][1] = kb + TEN;
        ga.out[2][0] = vb; ga.out[2][1] = vb + TEN;
        ga.X1[0] = ga.X1[1] = nullptr;
        ga.res[0] = ga.res[1] = nullptr;
        ga.M = 256; ga.K = 256; ga.K0 = 256; ga.use_bn = 0; ga.mtiles = 4;
        ga.bn_emit = 0;
        gemm_tc<<<dim3(32, 12, 2), 128, GEMM_SMEM>>>(ga);

        // attention -> g_msg
        attn_kernel<<<dim3(16, 8, 2), 256, ATTN_SMEM>>>();

        // h = [W1a | W1b*Wm] [x; attnout] + b1eff, with fused BN partials
        ga.Whi[0] = W1_hi; ga.Wlo[0] = W1_lo; ga.bias[0] = b1e_i;
        ga.X0[0][0] = xa; ga.X0[0][1] = xb;
        ga.X1[0] = msgb; ga.X1[1] = msgb + TEN;
        ga.out[0][0] = hb; ga.out[0][1] = hb + HTEN;
        ga.M = 512; ga.K = 512; ga.K0 = 256; ga.use_bn = 0; ga.mtiles = 8;
        ga.bn_emit = 1;
        gemm_tc<<<dim3(32, 8, 2), 128, GEMM_SMEM>>>(ga);
        ga.bn_emit = 0;

        // BN finalize (partials -> scale/shift)
        bn_finalize_kernel<<<dim3(512, 2), 64>>>(g1_i, be_i);

        // out = res + W2 relu(BN(h)) + b2
        ga.Whi[0] = W2_hi; ga.Wlo[0] = W2_lo; ga.bias[0] = b2_i;
        ga.X0[0][0] = hb; ga.X0[0][1] = hb + HTEN;
        ga.X1[0] = ga.X1[1] = nullptr;
        ga.res[0] = ra; ga.res[1] = rb;
        ga.out[0][0] = oa; ga.out[0][1] = ob;
        ga.M = 256; ga.K = 512; ga.K0 = 512; ga.use_bn = 1; ga.mtiles = 4;
        gemm_tc<<<dim3(32, 4, 2), 128, GEMM_SMEM>>>(ga);
        ga.res[0] = ga.res[1] = nullptr;

        xa = oa; xb = ob;
    }
}

// round 16
// speedup vs baseline: 1.2076x; 1.0505x over previous
#include <cuda_runtime.h>
#include <math.h>

// ---------------------------------------------------------------------------
// AttentionalGNN: L=18 layers, D=256, H=4 (head dim 64), B=2, N=1024.
// Round 16: qkv/W1 GEMMs move to 128x64x32 block tile (4 warps, warp tile
// 64x32) to halve per-mma fragment overhead. W2 keeps the 64x64 kernel.
// Everything else = round-15 (BN fused partials, Wm folded into W1).
// ---------------------------------------------------------------------------

#define BB   2
#define DD   256
#define NN   1024
#define TEN  (BB*DD*NN)
#define HTEN (BB*512*NN)

__device__ float g_q  [2*TEN];
__device__ float g_k  [2*TEN];
__device__ float g_v  [2*TEN];
__device__ float g_msg[2*TEN];
__device__ float g_h  [2*HTEN];
__device__ float g_stats[2*512*2];
__device__ float g_b1eff[18*512];
__device__ float g_bnpart[2*512*64*2];

#define SZ_D  (18L*256*256)
#define SZ_1  (18L*512*512)
#define SZ_2  (18L*256*512)
#define OFF_WQ 0L
#define OFF_WK (SZ_D)
#define OFF_WV (2*SZ_D)
#define OFF_WM (3*SZ_D)
#define OFF_W1 (4*SZ_D)
#define OFF_W2 (4*SZ_D + SZ_1)
#define TOTW   (4*SZ_D + SZ_1 + SZ_2)
__device__ float g_whi[TOTW];
__device__ float g_wlo[TOTW];

__device__ __forceinline__ float to_tf32(float x) {
    unsigned u;
    asm("cvt.rna.tf32.f32 %0, %1;" : "=r"(u) : "f"(x));
    return __uint_as_float(u);
}

#define MMA_TF32(acc, af, bf)                                                  \
    asm volatile(                                                              \
        "mma.sync.aligned.m16n8k8.row.col.f32.tf32.tf32.f32 "                  \
        "{%0,%1,%2,%3}, {%4,%5,%6,%7}, {%8,%9}, {%0,%1,%2,%3};"                \
        : "+f"(acc[0]), "+f"(acc[1]), "+f"(acc[2]), "+f"(acc[3])               \
        : "r"(af[0]), "r"(af[1]), "r"(af[2]), "r"(af[3]),                      \
          "r"(bf[0]), "r"(bf[1]))

__device__ __forceinline__ void cpa16(float* dst, const float* src) {
    unsigned sa = (unsigned)__cvta_generic_to_shared(dst);
    asm volatile("cp.async.ca.shared.global [%0], [%1], 16;" :: "r"(sa), "l"(src));
}

__device__ __forceinline__ float expq(float x) {
    x = fmaxf(x, -80.f);
    float t = fmaf(x, 1.4426950408889634f, 12582912.f);
    float n = t - 12582912.f;
    float f = fmaf(x, 1.4426950408889634f, -n);
    float p = 0.0001540353039338161f;
    p = fmaf(p, f, 0.0013333558146428443f);
    p = fmaf(p, f, 0.009618129107628477f);
    p = fmaf(p, f, 0.05550410866482158f);
    p = fmaf(p, f, 0.2402265069591007f);
    p = fmaf(p, f, 0.6931471805599453f);
    p = fmaf(p, f, 1.0f);
    int ni = __float_as_int(t) - 0x4B400000;
    return __int_as_float(__float_as_int(p) + (ni << 23));
}

// ---------------------------------------------------------------------------
// Weight pre-split
// ---------------------------------------------------------------------------
__global__ __launch_bounds__(256) void presplit_kernel(
    const float* __restrict__ Wq, const float* __restrict__ Wk,
    const float* __restrict__ Wv, const float* __restrict__ Wm,
    const float* __restrict__ W1, const float* __restrict__ W2) {
    long i = ((long)blockIdx.x * 256 + threadIdx.x) * 4;
    if (i >= TOTW) return;
    const float* src; long off = i;
    if      (i < OFF_WK) { src = Wq; }
    else if (i < OFF_WV) { src = Wk; off = i - OFF_WK; }
    else if (i < OFF_WM) { src = Wv; off = i - OFF_WV; }
    else if (i < OFF_W1) { src = Wm; off = i - OFF_WM; }
    else if (i < OFF_W2) { src = W1; off = i - OFF_W1; }
    else                 { src = W2; off = i - OFF_W2; }
    float4 w = *(const float4*)(src + off);
    float4 h, l;
    h.x = to_tf32(w.x); l.x = w.x - h.x;
    h.y = to_tf32(w.y); l.y = w.y - h.y;
    h.z = to_tf32(w.z); l.z = w.z - h.z;
    h.w = to_tf32(w.w); l.w = w.w - h.w;
    *(float4*)(g_whi + i) = h;
    *(float4*)(g_wlo + i) = l;
}

// ---------------------------------------------------------------------------
// W1m precompute (unchanged from r15).
// ---------------------------------------------------------------------------
__global__ __launch_bounds__(128) void fuse_w1m_kernel(
    const float* __restrict__ W1, const float* __restrict__ Wm) {
    __shared__ float Ah[64][36], Al[64][36];
    __shared__ float Bh[32][68], Bl[32][68];
    const int layer = blockIdx.z;
    const int n0 = blockIdx.x << 6;
    const int m0 = blockIdx.y << 6;
    const float* W1p = W1 + (size_t)layer * 262144;
    const float* Wmp = Wm + (size_t)layer * 65536;
    const int tid = threadIdx.x;
    const int warp = tid >> 5, lane = tid & 31;
    const int wm = (warp >> 1) << 5;
    const int wn = (warp & 1) << 5;
    const int g = lane >> 2, t = lane & 3;

    float acc[2][4][4];
    #pragma unroll
    for (int mi = 0; mi < 2; mi++)
        #pragma unroll
        for (int ni = 0; ni < 4; ni++)
            #pragma unroll
            for (int r = 0; r < 4; r++) acc[mi][ni][r] = 0.f;

    for (int k0 = 0; k0 < 256; k0 += 32) {
        #pragma unroll
        for (int e = tid; e < 512; e += 128) {
            int m  = e >> 3;
            int kq = (e & 7) << 2;
            float4 w = *(const float4*)&W1p[(size_t)(m0 + m) * 512 + 256 + k0 + kq];
            float wa[4] = {w.x, w.y, w.z, w.w};
            #pragma unroll
            for (int q = 0; q < 4; q++) {
                float hi = to_tf32(wa[q]);
                Ah[m][kq + q] = hi;
                Al[m][kq + q] = wa[q] - hi;
            }
        }
        #pragma unroll
        for (int e = tid; e < 512; e += 128) {
            int kk = e >> 4;
            int nq = (e & 15) << 2;
            float4 v = *(const float4*)&Wmp[(size_t)(k0 + kk) * 256 + n0 + nq];
            float va[4] = {v.x, v.y, v.z, v.w};
            #pragma unroll
            for (int q = 0; q < 4; q++) {
                float hi = to_tf32(va[q]);
                Bh[kk][nq + q] = hi;
                Bl[kk][nq + q] = va[q] - hi;
            }
        }
        __syncthreads();
        #pragma unroll
        for (int kk = 0; kk < 32; kk += 8) {
            unsigned afh[2][4], afl[2][4];
            #pragma unroll
            for (int mi = 0; mi < 2; mi++) {
                int r0 = wm + mi * 16 + g;
                afh[mi][0] = __float_as_uint(Ah[r0    ][kk + t    ]);
                afh[mi][1] = __float_as_uint(Ah[r0 + 8][kk + t    ]);
                afh[mi][2] = __float_as_uint(Ah[r0    ][kk + t + 4]);
                afh[mi][3] = __float_as_uint(Ah[r0 + 8][kk + t + 4]);
                afl[mi][0] = __float_as_uint(Al[r0    ][kk + t    ]);
                afl[mi][1] = __float_as_uint(Al[r0 + 8][kk + t    ]);
                afl[mi][2] = __float_as_uint(Al[r0    ][kk + t + 4]);
                afl[mi][3] = __float_as_uint(Al[r0 + 8][kk + t + 4]);
            }
            #pragma unroll
            for (int ni = 0; ni < 4; ni++) {
                int c = wn + ni * 8 + g;
                unsigned bh2[2] = {__float_as_uint(Bh[kk + t][c]),
                                   __float_as_uint(Bh[kk + t + 4][c])};
                unsigned bl2[2] = {__float_as_uint(Bl[kk + t][c]),
                                   __float_as_uint(Bl[kk + t + 4][c])};
                #pragma unroll
                for (int mi = 0; mi < 2; mi++) {
                    MMA_TF32(acc[mi][ni], afh[mi], bl2);
                    MMA_TF32(acc[mi][ni], afl[mi], bh2);
                    MMA_TF32(acc[mi][ni], afh[mi], bh2);
                }
            }
        }
        __syncthreads();
    }

    size_t base = OFF_W1 + (size_t)layer * 262144;
    #pragma unroll
    for (int mi = 0; mi < 2; mi++) {
        #pragma unroll
        for (int half = 0; half < 2; half++) {
            int m = m0 + wm + mi * 16 + g + half * 8;
            #pragma unroll
            for (int ni = 0; ni < 4; ni++) {
                int col = n0 + wn + ni * 8 + 2 * t;
                size_t off = base + (size_t)m * 512 + 256 + col;
                float v0 = acc[mi][ni][2 * half + 0];
                float v1 = acc[mi][ni][2 * half + 1];
                float h0 = to_tf32(v0), h1 = to_tf32(v1);
                *(float2*)(g_whi + off) = make_float2(h0, h1);
                *(float2*)(g_wlo + off) = make_float2(v0 - h0, v1 - h1);
            }
        }
    }
}

__global__ __launch_bounds__(512) void b1eff_kernel(
    const float* __restrict__ W1, const float* __restrict__ b1,
    const float* __restrict__ bm) {
    int layer = blockIdx.x;
    int m = threadIdx.x;
    const float* w = W1 + (size_t)layer * 262144 + (size_t)m * 512 + 256;
    const float* bmp = bm + layer * 256;
    float s = b1[layer * 512 + m];
    for (int o = 0; o < 256; o++) s = fmaf(w[o], bmp[o], s);
    g_b1eff[layer * 512 + m] = s;
}

// ---------------------------------------------------------------------------
// Common GEMM args.
// ---------------------------------------------------------------------------
struct GArgs {
    const float* Whi[3];
    const float* Wlo[3];
    const float* bias[3];
    const float* X0[3][2];
    const float* X1[2];
    const float* res[2];
    const float* bnp[2];
    float*       out[3][2];
    int M, K, K0, use_bn, mtiles, bn_emit;
};

// ---------------------------------------------------------------------------
// 64x64x32 GEMM (r12 config) — used for W2 (and any BN-consuming GEMM).
// ---------------------------------------------------------------------------
#define GEMM_SMEM (13696 * 4)

__global__ __launch_bounds__(128) void gemm_tc(GArgs a) {
    extern __shared__ __align__(16) float smem[];
    const int s   = blockIdx.z;
    const int jt  = blockIdx.x;
    const int b2  = jt >> 4;
    const int n0  = (jt & 15) << 6;
    const int mat = blockIdx.y / a.mtiles;
    const int m0  = (blockIdx.y % a.mtiles) << 6;
    const int tid = threadIdx.x;
    const int warp = tid >> 5, lane = tid & 31;
    const int wm = (warp >> 1) << 5;
    const int wn = (warp & 1) << 5;
    const int g = lane >> 2, t = lane & 3;

    const int K = a.K, K0 = a.K0, M = a.M;
    const int use_bn = a.use_bn;
    const float* __restrict__ Whi = a.Whi[mat];
    const float* __restrict__ Wlo = a.Wlo[mat];
    const float* __restrict__ X0  = a.X0[mat][s];
    const float* __restrict__ X1  = a.X1[s];
    const float* __restrict__ bnp = a.bnp[s];

    float acc[2][4][4];
    #pragma unroll
    for (int mi = 0; mi < 2; mi++)
        #pragma unroll
        for (int ni = 0; ni < 4; ni++)
            #pragma unroll
            for (int r = 0; r < 4; r++) acc[mi][ni][r] = 0.f;

    auto load_tile = [&](int k0, int buf) {
        float* AHb = smem + buf * 2304;
        float* ALb = smem + 4608 + buf * 2304;
        float* BSb = smem + 9216 + buf * 2176;
        float* BNb = smem + 13568 + buf * 64;
        #pragma unroll
        for (int e = tid; e < 512; e += 128) {
            int m  = e >> 3;
            int kq = (e & 7) << 2;
            size_t woff = (size_t)(m0 + m) * K + k0 + kq;
            cpa16(AHb + m * 36 + kq, Whi + woff);
            cpa16(ALb + m * 36 + kq, Wlo + woff);
        }
        #pragma unroll
        for (int e = tid; e < 512; e += 128) {
            int kk = e >> 4;
            int nq = (e & 15) << 2;
            int k = k0 + kk;
            const float* src = (k < K0)
                ? X0 + ((size_t)b2 * K0 + k) * NN + n0 + nq
                : X1 + ((size_t)b2 * (K - K0) + (k - K0)) * NN + n0 + nq;
            cpa16(BSb + kk * 68 + nq, src);
        }
        if (use_bn && tid < 64) BNb[tid] = bnp[2 * k0 + tid];
        asm volatile("cp.async.commit_group;" ::: "memory");
    };

    const int niter = K >> 5;
    load_tile(0, 0);

    for (int it = 0; it < niter; it++) {
        const int buf = it & 1;
        if (it + 1 < niter) {
            load_tile((it + 1) << 5, buf ^ 1);
            asm volatile("cp.async.wait_group 1;" ::: "memory");
        } else {
            asm volatile("cp.async.wait_group 0;" ::: "memory");
        }
        __syncthreads();

        const float* AHb = smem + buf * 2304;
        const float* ALb = smem + 4608 + buf * 2304;
        const float* BSb = smem + 9216 + buf * 2176;
        const float* BNb = smem + 13568 + buf * 64;

        #pragma unroll
        for (int kk = 0; kk < 32; kk += 8) {
            unsigned afh[2][4], afl[2][4];
            #pragma unroll
            for (int mi = 0; mi < 2; mi++) {
                int r0 = wm + mi * 16 + g;
                afh[mi][0] = __float_as_uint(AHb[(r0    ) * 36 + kk + t    ]);
                afh[mi][1] = __float_as_uint(AHb[(r0 + 8) * 36 + kk + t    ]);
                afh[mi][2] = __float_as_uint(AHb[(r0    ) * 36 + kk + t + 4]);
                afh[mi][3] = __float_as_uint(AHb[(r0 + 8) * 36 + kk + t + 4]);
                afl[mi][0] = __float_as_uint(ALb[(r0    ) * 36 + kk + t    ]);
                afl[mi][1] = __float_as_uint(ALb[(r0 + 8) * 36 + kk + t    ]);
                afl[mi][2] = __float_as_uint(ALb[(r0    ) * 36 + kk + t + 4]);
                afl[mi][3] = __float_as_uint(ALb[(r0 + 8) * 36 + kk + t + 4]);
            }
            float sc0 = 1.f, sh0 = 0.f, sc1 = 1.f, sh1 = 0.f;
            if (use_bn) {
                sc0 = BNb[2 * (kk + t)];     sh0 = BNb[2 * (kk + t) + 1];
                sc1 = BNb[2 * (kk + t + 4)]; sh1 = BNb[2 * (kk + t + 4) + 1];
            }
            #pragma unroll
            for (int ni = 0; ni < 4; ni++) {
                int c = wn + ni * 8 + g;
                float b0 = BSb[(kk + t    ) * 68 + c];
                float b1 = BSb[(kk + t + 4) * 68 + c];
                if (use_bn) {
                    b0 = fmaxf(fmaf(b0, sc0, sh0), 0.f);
                    b1 = fmaxf(fmaf(b1, sc1, sh1), 0.f);
                }
                float h0 = to_tf32(b0), h1 = to_tf32(b1);
                unsigned bh2[2] = {__float_as_uint(h0), __float_as_uint(h1)};
                unsigned bl2[2] = {__float_as_uint(b0 - h0), __float_as_uint(b1 - h1)};
                #pragma unroll
                for (int mi = 0; mi < 2; mi++) {
                    MMA_TF32(acc[mi][ni], afh[mi], bl2);
                    MMA_TF32(acc[mi][ni], afl[mi], bh2);
                    MMA_TF32(acc[mi][ni], afh[mi], bh2);
                }
            }
        }
        __syncthreads();
    }

    const float* resp = a.res[s];
    const float* biasp = a.bias[mat];
    float* outp = a.out[mat][s];
    #pragma unroll
    for (int mi = 0; mi < 2; mi++) {
        #pragma unroll
        for (int half = 0; half < 2; half++) {
            int m = m0 + wm + mi * 16 + g + half * 8;
            float bb = biasp[m];
            #pragma unroll
            for (int ni = 0; ni < 4; ni++) {
                int col = n0 + wn + ni * 8 + 2 * t;
                size_t off = ((size_t)b2 * M + m) * NN + col;
                float2 c;
                c.x = acc[mi][ni][2 * half + 0] + bb;
                c.y = acc[mi][ni][2 * half + 1] + bb;
                if (resp) {
                    float2 r = *(const float2*)(resp + off);
                    c.x += r.x; c.y += r.y;
                }
                *(float2*)(outp + off) = c;
            }
        }
    }
}

// ---------------------------------------------------------------------------
// 128x64x32 GEMM (4 warps, warp tile 64x32) — used for qkv and W1.
// Smem (floats): AH 2x128x36 = 9216 | AL 9216 | BS 2x2176 = 4352 | BN 2x64
//   total 22912 floats = 91648 B -> 2 blocks/SM.
// ---------------------------------------------------------------------------
#define GEMM128_SMEM (22912 * 4)

__global__ __launch_bounds__(128) void gemm_tc128(GArgs a) {
    extern __shared__ __align__(16) float smem[];
    // AH: 0 + buf*4608 | AL: 9216 + buf*4608 | BS: 18432 + buf*2176 | BN: 22784 + buf*64

    const int s   = blockIdx.z;
    const int jt  = blockIdx.x;
    const int b2  = jt >> 4;
    const int n0  = (jt & 15) << 6;
    const int mat = blockIdx.y / a.mtiles;
    const int m0  = (blockIdx.y % a.mtiles) << 7;
    const int tid = threadIdx.x;
    const int warp = tid >> 5, lane = tid & 31;
    const int wm = (warp >> 1) << 6;   // 0 / 64
    const int wn = (warp & 1) << 5;    // 0 / 32
    const int g = lane >> 2, t = lane & 3;

    const int K = a.K, K0 = a.K0, M = a.M;
    const float* __restrict__ Whi = a.Whi[mat];
    const float* __restrict__ Wlo = a.Wlo[mat];
    const float* __restrict__ X0  = a.X0[mat][s];
    const float* __restrict__ X1  = a.X1[s];

    float acc[4][4][4];
    #pragma unroll
    for (int mi = 0; mi < 4; mi++)
        #pragma unroll
        for (int ni = 0; ni < 4; ni++)
            #pragma unroll
            for (int r = 0; r < 4; r++) acc[mi][ni][r] = 0.f;

    auto load_tile = [&](int k0, int buf) {
        float* AHb = smem + buf * 4608;
        float* ALb = smem + 9216 + buf * 4608;
        float* BSb = smem + 18432 + buf * 2176;
        #pragma unroll
        for (int e = tid; e < 1024; e += 128) {
            int m  = e >> 3;
            int kq = (e & 7) << 2;
            size_t woff = (size_t)(m0 + m) * K + k0 + kq;
            cpa16(AHb + m * 36 + kq, Whi + woff);
            cpa16(ALb + m * 36 + kq, Wlo + woff);
        }
        #pragma unroll
        for (int e = tid; e < 512; e += 128) {
            int kk = e >> 4;
            int nq = (e & 15) << 2;
            int k = k0 + kk;
            const float* src = (k < K0)
                ? X0 + ((size_t)b2 * K0 + k) * NN + n0 + nq
                : X1 + ((size_t)b2 * (K - K0) + (k - K0)) * NN + n0 + nq;
            cpa16(BSb + kk * 68 + nq, src);
        }
        asm volatile("cp.async.commit_group;" ::: "memory");
    };

    const int niter = K >> 5;
    load_tile(0, 0);

    for (int it = 0; it < niter; it++) {
        const int buf = it & 1;
        if (it + 1 < niter) {
            load_tile((it + 1) << 5, buf ^ 1);
            asm volatile("cp.async.wait_group 1;" ::: "memory");
        } else {
            asm volatile("cp.async.wait_group 0;" ::: "memory");
        }
        __syncthreads();

        const float* AHb = smem + buf * 4608;
        const float* ALb = smem + 9216 + buf * 4608;
        const float* BSb = smem + 18432 + buf * 2176;

        #pragma unroll
        for (int kk = 0; kk < 32; kk += 8) {
            unsigned afh[4][4], afl[4][4];
            #pragma unroll
            for (int mi = 0; mi < 4; mi++) {
                int r0 = wm + mi * 16 + g;
                afh[mi][0] = __float_as_uint(AHb[(r0    ) * 36 + kk + t    ]);
                afh[mi][1] = __float_as_uint(AHb[(r0 + 8) * 36 + kk + t    ]);
                afh[mi][2] = __float_as_uint(AHb[(r0    ) * 36 + kk + t + 4]);
                afh[mi][3] = __float_as_uint(AHb[(r0 + 8) * 36 + kk + t + 4]);
                afl[mi][0] = __float_as_uint(ALb[(r0    ) * 36 + kk + t    ]);
                afl[mi][1] = __float_as_uint(ALb[(r0 + 8) * 36 + kk + t    ]);
                afl[mi][2] = __float_as_uint(ALb[(r0    ) * 36 + kk + t + 4]);
                afl[mi][3] = __float_as_uint(ALb[(r0 + 8) * 36 + kk + t + 4]);
            }
            #pragma unroll
            for (int ni = 0; ni < 4; ni++) {
                int c = wn + ni * 8 + g;
                float b0 = BSb[(kk + t    ) * 68 + c];
                float b1 = BSb[(kk + t + 4) * 68 + c];
                float h0 = to_tf32(b0), h1 = to_tf32(b1);
                unsigned bh2[2] = {__float_as_uint(h0), __float_as_uint(h1)};
                unsigned bl2[2] = {__float_as_uint(b0 - h0), __float_as_uint(b1 - h1)};
                #pragma unroll
                for (int mi = 0; mi < 4; mi++) {
                    MMA_TF32(acc[mi][ni], afh[mi], bl2);
                    MMA_TF32(acc[mi][ni], afl[mi], bh2);
                    MMA_TF32(acc[mi][ni], afh[mi], bh2);
                }
            }
        }
        __syncthreads();
    }

    const float* resp = a.res[s];
    const float* biasp = a.bias[mat];
    float* outp = a.out[mat][s];
    float rsum[4][2] = {}, rsq[4][2] = {};
    #pragma unroll
    for (int mi = 0; mi < 4; mi++) {
        #pragma unroll
        for (int half = 0; half < 2; half++) {
            int m = m0 + wm + mi * 16 + g + half * 8;
            float bb = biasp[m];
            #pragma unroll
            for (int ni = 0; ni < 4; ni++) {
                int col = n0 + wn + ni * 8 + 2 * t;
                size_t off = ((size_t)b2 * M + m) * NN + col;
                float2 c;
                c.x = acc[mi][ni][2 * half + 0] + bb;
                c.y = acc[mi][ni][2 * half + 1] + bb;
                if (resp) {
                    float2 r = *(const float2*)(resp + off);
                    c.x += r.x; c.y += r.y;
                }
                *(float2*)(outp + off) = c;
                if (a.bn_emit) {
                    rsum[mi][half] += c.x + c.y;
                    rsq[mi][half] = fmaf(c.x, c.x, fmaf(c.y, c.y, rsq[mi][half]));
                }
            }
        }
    }
    if (a.bn_emit) {
        #pragma unroll
        for (int mi = 0; mi < 4; mi++)
            #pragma unroll
            for (int half = 0; half < 2; half++) {
                float s1 = rsum[mi][half], s2 = rsq[mi][half];
                s1 += __shfl_xor_sync(0xffffffffu, s1, 1);
                s2 += __shfl_xor_sync(0xffffffffu, s2, 1);
                s1 += __shfl_xor_sync(0xffffffffu, s1, 2);
                s2 += __shfl_xor_sync(0xffffffffu, s2, 2);
                if (t == 0) {
                    int m = m0 + wm + mi * 16 + g + half * 8;
                    int p = jt * 2 + (warp & 1);
                    *(float2*)&g_bnpart[(((size_t)s * 512 + m) * 64 + p) * 2] =
                        make_float2(s1, s2);
                }
            }
    }
}

// ---------------------------------------------------------------------------
// BN finalize (unchanged).
// ---------------------------------------------------------------------------
__global__ __launch_bounds__(64) void bn_finalize_kernel(
    const float* __restrict__ g1, const float* __restrict__ be1) {
    const int c = blockIdx.x;
    const int s = blockIdx.y;
    const int tid = threadIdx.x;
    float2 v = *(const float2*)&g_bnpart[(((size_t)s * 512 + c) * 64 + tid) * 2];
    float S = v.x, Q = v.y;
    #pragma unroll
    for (int w = 16; w; w >>= 1) {
        S += __shfl_xor_sync(0xffffffffu, S, w);
        Q += __shfl_xor_sync(0xffffffffu, Q, w);
    }
    __shared__ float sS[2], sQ[2];
    if ((tid & 31) == 0) { sS[tid >> 5] = S; sQ[tid >> 5] = Q; }
    __syncthreads();
    if (tid == 0) {
        S = sS[0] + sS[1];
        Q = sQ[0] + sQ[1];
        float mean = S * (1.f / 2048.f);
        float var  = Q * (1.f / 2048.f) - mean * mean;
        float rstd = rsqrtf(var + 1e-5f);
        float sc = rstd * g1[c];
        float sh = be1[c] - mean * sc;
        g_stats[(s * 512 + c) * 2 + 0] = sc;
        g_stats[(s * 512 + c) * 2 + 1] = sh;
    }
}

// ---------------------------------------------------------------------------
// Tensor-core flash attention (3xTF32) — r12 version, unchanged.
// ---------------------------------------------------------------------------
#define ATTN_SMEM (6 * 64 * 68 * 4)

__global__ __launch_bounds__(256) void attn_kernel() {
    extern __shared__ __align__(16) float sm[];
    float (*Qh)[68]  = (float(*)[68])(sm);
    float (*Ql)[68]  = (float(*)[68])(sm + 4352);
    float (*Ks0)[68] = (float(*)[68])(sm + 2 * 4352);
    float (*Ks1)[68] = (float(*)[68])(sm + 3 * 4352);
    float (*Vs)[68]  = (float(*)[68])(sm + 4 * 4352);
    float (*Ps)[68]  = (float(*)[68])(sm + 5 * 4352);
    __shared__ float red_max[2][4][16];
    __shared__ float red_sum[2][4][16];

    const int qt = blockIdx.x;
    const int bh = blockIdx.y;
    const int s  = blockIdx.z;
    const int b2 = bh >> 2, h = bh & 3;
    const int q0 = qt << 6;
    const int tid = threadIdx.x;
    const int warp = tid >> 5, lane = tid & 31;
    const int g = lane >> 2, t = lane & 3;
    const int qw = warp >> 1, kw = warp & 1;
    const int qcol = qw << 4;
    const int kcol = kw << 5;

    size_t base = (size_t)s * TEN + (size_t)b2 * (DD * NN);
    const float* __restrict__ qp = g_q + base;
    const float* __restrict__ kp = g_k + base;
    const float* __restrict__ vp = g_v + base;
    float* mp = g_msg + base;

    for (int e = tid; e < 4096; e += 256) {
        int qi = e & 63, d = e >> 6;
        float v = qp[(size_t)(d * 4 + h) * NN + q0 + qi] * 0.125f;
        float hi = to_tf32(v);
        Qh[d][qi] = hi;
        Ql[d][qi] = v - hi;
    }

    for (int e = tid; e < 1024; e += 256) {
        int d  = e >> 4;
        int c4 = (e & 15) << 2;
        cpa16(&Ks0[d][c4], kp + (size_t)(d * 4 + h) * NN + c4);
    }
    asm volatile("cp.async.commit_group;" ::: "memory");
    for (int e = tid; e < 1024; e += 256) {
        int d  = e >> 4;
        int c4 = (e & 15) << 2;
        cpa16(&Vs[d][c4], vp + (size_t)(d * 4 + h) * NN + c4);
    }
    asm volatile("cp.async.commit_group;" ::: "memory");

    float oacc[4][4] = {};
    float mi2[2] = {-1e30f, -1e30f};
    float li2[2] = {0.f, 0.f};

    for (int kt = 0; kt < 16; kt++) {
        float (*Kb)[68] = (kt & 1) ? Ks1 : Ks0;
        float (*Kn)[68] = (kt & 1) ? Ks0 : Ks1;

        asm volatile("cp.async.wait_group 1;" ::: "memory");
        __syncthreads();

        if (kt + 1 < 16) {
            int m1 = (kt + 1) << 6;
            for (int e = tid; e < 1024; e += 256) {
                int d  = e >> 4;
                int c4 = (e & 15) << 2;
                cpa16(&Kn[d][c4], kp + (size_t)(d * 4 + h) * NN + m1 + c4);
            }
            asm volatile("cp.async.commit_group;" ::: "memory");
        }

        float sacc[4][4] = {};
        #pragma unroll
        for (int kk = 0; kk < 64; kk += 8) {
            unsigned ah[4], al[4];
            ah[0] = __float_as_uint(Qh[kk + t    ][qcol + g    ]);
            ah[1] = __float_as_uint(Qh[kk + t    ][qcol + g + 8]);
            ah[2] = __float_as_uint(Qh[kk + t + 4][qcol + g    ]);
            ah[3] = __float_as_uint(Qh[kk + t + 4][qcol + g + 8]);
            al[0] = __float_as_uint(Ql[kk + t    ][qcol + g    ]);
            al[1] = __float_as_uint(Ql[kk + t    ][qcol + g + 8]);
            al[2] = __float_as_uint(Ql[kk + t + 4][qcol + g    ]);
            al[3] = __float_as_uint(Ql[kk + t + 4][qcol + g + 8]);
            #pragma unroll
            for (int ni = 0; ni < 4; ni++) {
                int c = kcol + ni * 8 + g;
                float b0 = Kb[kk + t    ][c];
                float b1 = Kb[kk + t + 4][c];
                float h0 = to_tf32(b0), h1 = to_tf32(b1);
                unsigned bh2[2] = {__float_as_uint(h0), __float_as_uint(h1)};
                unsigned bl2[2] = {__float_as_uint(b0 - h0), __float_as_uint(b1 - h1)};
                MMA_TF32(sacc[ni], ah, bl2);
                MMA_TF32(sacc[ni], al, bh2);
                MMA_TF32(sacc[ni], ah, bh2);
            }
        }

        float mloc[2] = {-1e30f, -1e30f};
        #pragma unroll
        for (int ni = 0; ni < 4; ni++) {
            mloc[0] = fmaxf(mloc[0], fmaxf(sacc[ni][0], sacc[ni][1]));
            mloc[1] = fmaxf(mloc[1], fmaxf(sacc[ni][2], sacc[ni][3]));
        }
        #pragma unroll
        for (int r = 0; r < 2; r++) {
            mloc[r] = fmaxf(mloc[r], __shfl_xor_sync(0xffffffffu, mloc[r], 1));
            mloc[r] = fmaxf(mloc[r], __shfl_xor_sync(0xffffffffu, mloc[r], 2));
        }
        if (t == 0) {
            red_max[kw][qw][g    ] = mloc[0];
            red_max[kw][qw][g + 8] = mloc[1];
        }
        __syncthreads();
        float mn[2], alpha[2];
        #pragma unroll
        for (int r = 0; r < 2; r++) {
            int row = g + r * 8;
            float mk = fmaxf(red_max[0][qw][row], red_max[1][qw][row]);
            mn[r] = fmaxf(mi2[r], mk);
            alpha[r] = expq(mi2[r] - mn[r]);
            mi2[r] = mn[r];
        }
        float rs[2] = {0.f, 0.f};
        #pragma unroll
        for (int ni = 0; ni < 4; ni++) {
            #pragma unroll
            for (int j = 0; j < 4; j++) {
                int r = j >> 1;
                float p = expq(sacc[ni][j] - mn[r]);
                sacc[ni][j] = p;
                rs[r] += p;
            }
        }
        #pragma unroll
        for (int r = 0; r < 2; r++) {
            rs[r] += __shfl_xor_sync(0xffffffffu, rs[r], 1);
            rs[r] += __shfl_xor_sync(0xffffffffu, rs[r], 2);
        }
        if (t == 0) {
            red_sum[kw][qw][g    ] = rs[0];
            red_sum[kw][qw][g + 8] = rs[1];
        }
        #pragma unroll
        for (int ni = 0; ni < 4; ni++) {
            #pragma unroll
            for (int r = 0; r < 2; r++) {
                int row = qcol + g + r * 8;
                int col = kcol + ni * 8 + 2 * t;
                *(float2*)&Ps[row][col] = make_float2(sacc[ni][2 * r], sacc[ni][2 * r + 1]);
            }
        }
        if (kt + 1 < 16) {
            asm volatile("cp.async.wait_group 1;" ::: "memory");
        } else {
            asm volatile("cp.async.wait_group 0;" ::: "memory");
        }
        __syncthreads();

        #pragma unroll
        for (int r = 0; r < 2; r++) {
            int row = g + r * 8;
            float rstot = red_sum[0][qw][row] + red_sum[1][qw][row];
            li2[r] = li2[r] * alpha[r] + rstot;
        }
        #pragma unroll
        for (int ni = 0; ni < 4; ni++) {
            oacc[ni][0] *= alpha[0]; oacc[ni][1] *= alpha[0];
            oacc[ni][2] *= alpha[1]; oacc[ni][3] *= alpha[1];
        }

        #pragma unroll
        for (int kk = 0; kk < 64; kk += 8) {
            float a0 = Ps[qcol + g    ][kk + t    ];
            float a1 = Ps[qcol + g + 8][kk + t    ];
            float a2 = Ps[qcol + g    ][kk + t + 4];
            float a3 = Ps[qcol + g + 8][kk + t + 4];
            float ah0 = to_tf32(a0), ah1 = to_tf32(a1);
            float ah2 = to_tf32(a2), ah3 = to_tf32(a3);
            unsigned ah[4] = {__float_as_uint(ah0), __float_as_uint(ah1),
                              __float_as_uint(ah2), __float_as_uint(ah3)};
            unsigned al[4] = {__float_as_uint(a0 - ah0), __float_as_uint(a1 - ah1),
                              __float_as_uint(a2 - ah2), __float_as_uint(a3 - ah3)};
            #pragma unroll
            for (int ni = 0; ni < 4; ni++) {
                int c = kcol + ni * 8 + g;
                float b0 = Vs[c][kk + t    ];
                float b1 = Vs[c][kk + t + 4];
                float h0 = to_tf32(b0), h1 = to_tf32(b1);
                unsigned bh2[2] = {__float_as_uint(h0), __float_as_uint(h1)};
                unsigned bl2[2] = {__float_as_uint(b0 - h0), __float_as_uint(b1 - h1)};
                MMA_TF32(oacc[ni], ah, bl2);
                MMA_TF32(oacc[ni], al, bh2);
                MMA_TF32(oacc[ni], ah, bh2);
            }
        }

        __syncthreads();
        if (kt + 1 < 16) {
            int m1 = (kt + 1) << 6;
            for (int e = tid; e < 1024; e += 256) {
                int d  = e >> 4;
                int c4 = (e & 15) << 2;
                cpa16(&Vs[d][c4], vp + (size_t)(d * 4 + h) * NN + m1 + c4);
            }
            asm volatile("cp.async.commit_group;" ::: "memory");
        }
    }

    float inv[2] = {1.f / li2[0], 1.f / li2[1]};
    #pragma unroll
    for (int ni = 0; ni < 4; ni++) {
        #pragma unroll
        for (int j = 0; j < 4; j++) {
            int r = j >> 1;
            int row_q = qcol + g + r * 8;
            int col_d = kcol + ni * 8 + 2 * t + (j & 1);
            Ps[col_d][row_q] = oacc[ni][j] * inv[r];
        }
    }
    __syncthreads();
    for (int e = tid; e < 4096; e += 256) {
        int qi = e & 63, d = e >> 6;
        mp[(size_t)(d * 4 + h) * NN + q0 + qi] = Ps[d][qi];
    }
}

// ---------------------------------------------------------------------------
// Host orchestration
// ---------------------------------------------------------------------------
extern "C" void kernel_launch(void* const* d_in, const int* in_sizes, int n_in,
                              void* d_out, int out_size) {
    const float* desc0 = (const float*)d_in[0];
    const float* desc1 = (const float*)d_in[1];
    const float* Wq  = (const float*)d_in[2];
    const float* bq  = (const float*)d_in[3];
    const float* Wk  = (const float*)d_in[4];
    const float* bk  = (const float*)d_in[5];
    const float* Wv  = (const float*)d_in[6];
    const float* bv  = (const float*)d_in[7];
    const float* Wm  = (const float*)d_in[8];
    const float* bm  = (const float*)d_in[9];
    const float* W1  = (const float*)d_in[10];
    const float* b1  = (const float*)d_in[11];
    const float* g1  = (const float*)d_in[12];
    const float* be1 = (const float*)d_in[13];
    const float* W2  = (const float*)d_in[14];
    const float* b2  = (const float*)d_in[15];
    float* out = (float*)d_out;

    float *qb, *kb, *vb, *msgb, *hb, *statsb, *whi, *wlo, *b1effb;
    cudaGetSymbolAddress((void**)&qb,    g_q);
    cudaGetSymbolAddress((void**)&kb,    g_k);
    cudaGetSymbolAddress((void**)&vb,    g_v);
    cudaGetSymbolAddress((void**)&msgb,  g_msg);
    cudaGetSymbolAddress((void**)&hb,    g_h);
    cudaGetSymbolAddress((void**)&statsb, g_stats);
    cudaGetSymbolAddress((void**)&whi,   g_whi);
    cudaGetSymbolAddress((void**)&wlo,   g_wlo);
    cudaGetSymbolAddress((void**)&b1effb, g_b1eff);

    cudaFuncSetAttribute(attn_kernel,
                         cudaFuncAttributeMaxDynamicSharedMemorySize, ATTN_SMEM);
    cudaFuncSetAttribute(gemm_tc,
                         cudaFuncAttributeMaxDynamicSharedMemorySize, GEMM_SMEM);
    cudaFuncSetAttribute(gemm_tc128,
                         cudaFuncAttributeMaxDynamicSharedMemorySize, GEMM128_SMEM);

    presplit_kernel<<<(int)((TOTW / 4 + 255) / 256), 256>>>(Wq, Wk, Wv, Wm, W1, W2);
    fuse_w1m_kernel<<<dim3(4, 8, 18), 128>>>(W1, Wm);
    b1eff_kernel<<<18, 512>>>(W1, b1, bm);

    cudaMemcpyAsync(out + 2 * (size_t)TEN, desc0, TEN * sizeof(float),
                    cudaMemcpyDeviceToDevice, 0);
    cudaMemcpyAsync(out + 3 * (size_t)TEN, desc1, TEN * sizeof(float),
                    cudaMemcpyDeviceToDevice, 0);

    const float* xa = desc0;
    const float* xb = desc1;

    for (int i = 0; i < 18; i++) {
        const float *sa, *sb, *ra, *rb;
        float *oa, *ob;
        if (i == 0) {
            sa = xa; sb = xb; ra = desc0; rb = desc1;
            oa = out;            ob = out + (size_t)TEN;
        } else if (i == 1) {
            sa = xb; sb = xa; ra = desc0; rb = desc1;
            oa = out + 4 * (size_t)TEN; ob = out + 5 * (size_t)TEN;
        } else {
            if ((i & 1) == 0) { sa = xa; sb = xb; }
            else              { sa = xb; sb = xa; }
            ra = xa; rb = xb;
            oa = out + (size_t)(2 + 2 * i) * TEN;
            ob = oa + (size_t)TEN;
        }

        const float* Wq_hi = whi + OFF_WQ + (size_t)i * 65536;
        const float* Wq_lo = wlo + OFF_WQ + (size_t)i * 65536;
        const float* Wk_hi = whi + OFF_WK + (size_t)i * 65536;
        const float* Wk_lo = wlo + OFF_WK + (size_t)i * 65536;
        const float* Wv_hi = whi + OFF_WV + (size_t)i * 65536;
        const float* Wv_lo = wlo + OFF_WV + (size_t)i * 65536;
        const float* W1_hi = whi + OFF_W1 + (size_t)i * 262144;
        const float* W1_lo = wlo + OFF_W1 + (size_t)i * 262144;
        const float* W2_hi = whi + OFF_W2 + (size_t)i * 131072;
        const float* W2_lo = wlo + OFF_W2 + (size_t)i * 131072;
        const float* bq_i = bq + (size_t)i * 256;
        const float* bk_i = bk + (size_t)i * 256;
        const float* bv_i = bv + (size_t)i * 256;
        const float* b1e_i = b1effb + (size_t)i * 512;
        const float* b2_i = b2 + (size_t)i * 256;
        const float* g1_i = g1 + (size_t)i * 512;
        const float* be_i = be1 + (size_t)i * 512;

        GArgs ga = {};
        ga.bnp[0] = statsb; ga.bnp[1] = statsb + 1024;

        // q/k/v merged (128-row tiles: mtiles = 256/128 = 2)
        ga.Whi[0] = Wq_hi; ga.Wlo[0] = Wq_lo; ga.bias[0] = bq_i;
        ga.Whi[1] = Wk_hi; ga.Wlo[1] = Wk_lo; ga.bias[1] = bk_i;
        ga.Whi[2] = Wv_hi; ga.Wlo[2] = Wv_lo; ga.bias[2] = bv_i;
        ga.X0[0][0] = xa; ga.X0[0][1] = xb;
        ga.X0[1][0] = sa; ga.X0[1][1] = sb;
        ga.X0[2][0] = sa; ga.X0[2][1] = sb;
        ga.out[0][0] = qb; ga.out[0][1] = qb + TEN;
        ga.out[1][0] = kb; ga.out[1][1] = kb + TEN;
        ga.out[2][0] = vb; ga.out[2][1] = vb + TEN;
        ga.X1[0] = ga.X1[1] = nullptr;
        ga.res[0] = ga.res[1] = nullptr;
        ga.M = 256; ga.K = 256; ga.K0 = 256; ga.use_bn = 0; ga.mtiles = 2;
        ga.bn_emit = 0;
        gemm_tc128<<<dim3(32, 6, 2), 128, GEMM128_SMEM>>>(ga);

        // attention -> g_msg
        attn_kernel<<<dim3(16, 8, 2), 256, ATTN_SMEM>>>();

        // h = [W1a | W1b*Wm] [x; attnout] + b1eff, with fused BN partials
        ga.Whi[0] = W1_hi; ga.Wlo[0] = W1_lo; ga.bias[0] = b1e_i;
        ga.X0[0][0] = xa; ga.X0[0][1] = xb;
        ga.X1[0] = msgb; ga.X1[1] = msgb + TEN;
        ga.out[0][0] = hb; ga.out[0][1] = hb + HTEN;
        ga.M = 512; ga.K = 512; ga.K0 = 256; ga.use_bn = 0; ga.mtiles = 4;
        ga.bn_emit = 1;
        gemm_tc128<<<dim3(32, 4, 2), 128, GEMM128_SMEM>>>(ga);
        ga.bn_emit = 0;

        // BN finalize (partials -> scale/shift)
        bn_finalize_kernel<<<dim3(512, 2), 64>>>(g1_i, be_i);

        // out = res + W2 relu(BN(h)) + b2  (64x64 kernel)
        ga.Whi[0] = W2_hi; ga.Wlo[0] = W2_lo; ga.bias[0] = b2_i;
        ga.X0[0][0] = hb; ga.X0[0][1] = hb + HTEN;
        ga.X1[0] = ga.X1[1] = nullptr;
        ga.res[0] = ra; ga.res[1] = rb;
        ga.out[0][0] = oa; ga.out[0][1] = ob;
        ga.M = 256; ga.K = 512; ga.K0 = 512; ga.use_bn = 1; ga.mtiles = 4;
        gemm_tc<<<dim3(32, 4, 2), 128, GEMM_SMEM>>>(ga);
        ga.res[0] = ga.res[1] = nullptr;

        xa = oa; xb = ob;
    }
}